// round 14
// baseline (speedup 1.0000x reference)
#include <cuda_runtime.h>
#include <cuda_bf16.h>
#include <cstdint>

#define DM 1024
#define NH 16
#define HD 64
#define BB 2
#define LL 2048
#define ML (BB * LL)  // 4096 total rows

// ---------------- scratch (no allocation allowed) ----------------
__device__ __nv_bfloat16 g_x0hi[ML * DM], g_x0lo[ML * DM];
__device__ __nv_bfloat16 g_x1hi[ML * DM], g_x1lo[ML * DM];
__device__ __nv_bfloat16 g_x2hi[ML * DM], g_x2lo[ML * DM];
__device__ __nv_bfloat16 g_w0hi[DM * DM], g_w0lo[DM * DM];
__device__ __nv_bfloat16 g_w1hi[DM * DM], g_w1lo[DM * DM];
__device__ __nv_bfloat16 g_w2hi[DM * DM], g_w2lo[DM * DM];
__device__ __nv_bfloat16 g_w3hi[DM * DM], g_w3lo[DM * DM];
__device__ __nv_bfloat16 g_qhi[ML * DM], g_qlo[ML * DM];
__device__ __nv_bfloat16 g_kchi[BB * NH * LL * HD], g_kclo[BB * NH * LL * HD];
__device__ __nv_bfloat16 g_vchi[BB * NH * LL * HD], g_vclo[BB * NH * LL * HD];
__device__ __nv_bfloat16 g_vthi[BB * NH * HD * LL], g_vtlo[BB * NH * HD * LL];
__device__ __nv_bfloat16 g_ahi[ML * DM], g_alo[ML * DM];  // flash output (split)
__device__ int g_cidx[BB * LL];
__device__ int g_nact[BB];

// ================= helpers (base compute_103 PTX only) ==========
__device__ __forceinline__ uint32_t smem_u32(const void* p) {
    uint32_t a;
    asm("{ .reg .u64 t; cvta.to.shared.u64 t, %1; cvt.u32.u64 %0, t; }" : "=r"(a) : "l"(p));
    return a;
}
__device__ __forceinline__ void ldm_x4(uint32_t* r, uint32_t addr) {
    asm volatile("ldmatrix.sync.aligned.m8n8.x4.shared.b16 {%0,%1,%2,%3}, [%4];"
                 : "=r"(r[0]), "=r"(r[1]), "=r"(r[2]), "=r"(r[3]) : "r"(addr));
}
__device__ __forceinline__ void ldm_x2(uint32_t* r, uint32_t addr) {
    asm volatile("ldmatrix.sync.aligned.m8n8.x2.shared.b16 {%0,%1}, [%2];"
                 : "=r"(r[0]), "=r"(r[1]) : "r"(addr));
}
__device__ __forceinline__ void mma16816(float* c, const uint32_t* a, const uint32_t* b) {
    asm volatile("mma.sync.aligned.m16n8k16.row.col.f32.bf16.bf16.f32 "
                 "{%0,%1,%2,%3}, {%4,%5,%6,%7}, {%8,%9}, {%0,%1,%2,%3};"
                 : "+f"(c[0]), "+f"(c[1]), "+f"(c[2]), "+f"(c[3])
                 : "r"(a[0]), "r"(a[1]), "r"(a[2]), "r"(a[3]), "r"(b[0]), "r"(b[1]));
}
__device__ __forceinline__ float ex2(float x) {
    float y;
    asm("ex2.approx.ftz.f32 %0, %1;" : "=f"(y) : "f"(x));
    return y;
}
__device__ __forceinline__ uint32_t pack2(__nv_bfloat16 a, __nv_bfloat16 b) {
    __nv_bfloat162 t = __halves2bfloat162(a, b);
    return *reinterpret_cast<uint32_t*>(&t);
}
#define CP16(d, s) asm volatile("cp.async.cg.shared.global [%0], [%1], 16;" :: "r"(d), "l"(s))
#define CPCOMMIT() asm volatile("cp.async.commit_group;" ::: "memory")
#define CPWAIT0()  asm volatile("cp.async.wait_group 0;" ::: "memory")

// =================================================================
// fused split: all 7 fp32 arrays -> bf16 hi/lo in one launch
// =================================================================
struct SP {
    const float* src[7];
    __nv_bfloat16* hi[7];
    __nv_bfloat16* lo[7];
    int n[7];
};

__global__ __launch_bounds__(256)
void split_all(SP sp)
{
    const int s = blockIdx.y;
    const float* __restrict__ x = sp.src[s];
    __nv_bfloat16* __restrict__ hi = sp.hi[s];
    __nv_bfloat16* __restrict__ lo = sp.lo[s];
    const int n = sp.n[s];
    const int stride = gridDim.x * 1024;
    for (int i = (blockIdx.x * 256 + threadIdx.x) * 4; i < n; i += stride) {
        float4 f = *reinterpret_cast<const float4*>(x + i);
        __nv_bfloat16 h0 = __float2bfloat16(f.x);
        __nv_bfloat16 h1 = __float2bfloat16(f.y);
        __nv_bfloat16 h2 = __float2bfloat16(f.z);
        __nv_bfloat16 h3 = __float2bfloat16(f.w);
        *reinterpret_cast<uint32_t*>(hi + i)     = pack2(h0, h1);
        *reinterpret_cast<uint32_t*>(hi + i + 2) = pack2(h2, h3);
        *reinterpret_cast<uint32_t*>(lo + i) =
            pack2(__float2bfloat16(f.x - __bfloat162float(h0)),
                  __float2bfloat16(f.y - __bfloat162float(h1)));
        *reinterpret_cast<uint32_t*>(lo + i + 2) =
            pack2(__float2bfloat16(f.z - __bfloat162float(h2)),
                  __float2bfloat16(f.w - __bfloat162float(h3)));
    }
}

// =================================================================
// mask compaction (deterministic)
// =================================================================
__global__ __launch_bounds__(256)
void compact_mask(const int* __restrict__ mask, int* __restrict__ cidx,
                  int* __restrict__ nact)
{
    int b = blockIdx.x, tid = threadIdx.x;
    __shared__ int ws[256];
    const int* mb = mask + b * LL;
    int base = tid * 8;
    int loc[8];
    int cnt = 0;
#pragma unroll
    for (int i = 0; i < 8; i++) { loc[i] = cnt; cnt += (mb[base + i] == 0); }
    ws[tid] = cnt;
    __syncthreads();
    if (tid == 0) {
        int acc = 0;
        for (int i = 0; i < 256; i++) { int t = ws[i]; ws[i] = acc; acc += t; }
        nact[b] = acc;
    }
    __syncthreads();
    int off = ws[tid];
#pragma unroll
    for (int i = 0; i < 8; i++)
        if (mb[base + i] == 0) cidx[b * LL + off + loc[i]] = base + i;
}

// =================================================================
// cp.async double-buffered GEMM, batched over z.
// =================================================================
#define LDK 40
#define GSTG 40960

struct GP {
    const __nv_bfloat16 *Ahi[3], *Alo[3], *Bhi[3], *Blo[3];
    const float* bias[3];
    float* Yf[3];
    __nv_bfloat16 *Yhi[3], *Ylo[3];
    float scale[3];
    int mode[3];
    int gather[3];
    const int* cidx;
    const int* nact;
};

__global__ __launch_bounds__(256, 2)
void gemm_mma2(GP p)
{
    extern __shared__ char smem[];
    __shared__ int sidx[128];
    const int z = blockIdx.z;
    const __nv_bfloat16* __restrict__ Ahi = p.Ahi[z];
    const __nv_bfloat16* __restrict__ Alo = p.Alo[z];
    const __nv_bfloat16* __restrict__ Bhi = p.Bhi[z];
    const __nv_bfloat16* __restrict__ Blo = p.Blo[z];
    const float* __restrict__ bias = p.bias[z];

    const int tid = threadIdx.x, lane = tid & 31, wid = tid >> 5;
    const int wm = wid & 1, wn = wid >> 1;
    const int bm = blockIdx.y * 128, bn = blockIdx.x * 128;
    const int gflag = p.gather[z];
    const int b = bm >> 11;  // batch (LL=2048)
    const uint32_t su = smem_u32(smem);

    if (gflag) {
        int na = p.nact[b];
        int bound = (na + 63) & ~63;
        int gi0 = bm & (LL - 1);
        if (gi0 >= bound) return;
        if (tid < 128) {
            int gi = gi0 + tid;
            int gcl = gi < na ? gi : na - 1;
            sidx[tid] = p.cidx[b * LL + gcl];
        }
        __syncthreads();
    }

    float acc[4][4][4];
#pragma unroll
    for (int mt = 0; mt < 4; mt++)
#pragma unroll
        for (int nt = 0; nt < 4; nt++)
#pragma unroll
            for (int e = 0; e < 4; e++) acc[mt][nt][e] = 0.f;

    const uint32_t aoff = (uint32_t)(((lane & 15) * LDK + (lane >> 4) * 8) * 2);
    const uint32_t boff = (uint32_t)(((lane & 7) * LDK + ((lane >> 3) & 1) * 8) * 2);

    auto issue = [&](int s, int c) {
        uint32_t sb = su + (uint32_t)s * GSTG;
        int k0 = c * 32;
#pragma unroll
        for (int rep = 0; rep < 2; rep++) {
            int ch = tid + rep * 256;              // 0..511: 128 rows x 4 segs (64B/row)
            int row = ch >> 2, seg = ch & 3;
            uint32_t doff = (uint32_t)(row * 80 + seg * 16);
            size_t arow = gflag ? (size_t)(b * LL + sidx[row]) : (size_t)(bm + row);
            size_t goA = arow * DM + k0 + seg * 8;
            size_t goB = (size_t)(bn + row) * DM + k0 + seg * 8;
            CP16(sb + doff,         Ahi + goA);
            CP16(sb + 10240 + doff, Alo + goA);
            CP16(sb + 20480 + doff, Bhi + goB);
            CP16(sb + 30720 + doff, Blo + goB);
        }
    };

    issue(0, 0);
    CPCOMMIT();

    for (int c = 0; c < 32; c++) {
        CPWAIT0();
        __syncthreads();
        if (c + 1 < 32) { issue((c + 1) & 1, c + 1); CPCOMMIT(); }
        const uint32_t sb = su + (uint32_t)(c & 1) * GSTG;
        const uint32_t uAh = sb, uAl = sb + 10240, uBh = sb + 20480, uBl = sb + 30720;
#pragma unroll
        for (int ks = 0; ks < 2; ks++) {
            const uint32_t kb = (uint32_t)(ks * 32);
            uint32_t ah[4][4], al[4][4], bh[4][2], bl[4][2];
#pragma unroll
            for (int mt = 0; mt < 4; mt++) {
                uint32_t r = (uint32_t)((wm * 64 + mt * 16) * LDK * 2) + aoff + kb;
                ldm_x4(ah[mt], uAh + r);
                ldm_x4(al[mt], uAl + r);
            }
#pragma unroll
            for (int nt = 0; nt < 4; nt++) {
                uint32_t r = (uint32_t)((wn * 32 + nt * 8) * LDK * 2) + boff + kb;
                ldm_x2(bh[nt], uBh + r);
                ldm_x2(bl[nt], uBl + r);
            }
#pragma unroll
            for (int mt = 0; mt < 4; mt++)
#pragma unroll
                for (int nt = 0; nt < 4; nt++) {
                    mma16816(acc[mt][nt], ah[mt], bh[nt]);
                    mma16816(acc[mt][nt], ah[mt], bl[nt]);
                    mma16816(acc[mt][nt], al[mt], bh[nt]);
                }
        }
    }

    const int mode = p.mode[z];
    if (mode == 0) {
        float* Y = p.Yf[z];
#pragma unroll
        for (int mt = 0; mt < 4; mt++) {
            int r0 = bm + wm * 64 + mt * 16 + (lane >> 2);
#pragma unroll
            for (int nt = 0; nt < 4; nt++) {
                int c0 = bn + wn * 32 + nt * 8 + (lane & 3) * 2;
                float bx = bias[c0], by = bias[c0 + 1];
                *reinterpret_cast<float2*>(Y + (size_t)r0 * DM + c0) =
                    make_float2(acc[mt][nt][0] + bx, acc[mt][nt][1] + by);
                *reinterpret_cast<float2*>(Y + (size_t)(r0 + 8) * DM + c0) =
                    make_float2(acc[mt][nt][2] + bx, acc[mt][nt][3] + by);
            }
        }
    } else if (mode == 1) {
        __nv_bfloat16* Yh = p.Yhi[z];
        __nv_bfloat16* Yl = p.Ylo[z];
        const float sc = p.scale[z];
#pragma unroll
        for (int mt = 0; mt < 4; mt++) {
            int r0 = bm + wm * 64 + mt * 16 + (lane >> 2);
#pragma unroll
            for (int nt = 0; nt < 4; nt++) {
                int c0 = bn + wn * 32 + nt * 8 + (lane & 3) * 2;
                float bx = bias[c0], by = bias[c0 + 1];
                float y0 = (acc[mt][nt][0] + bx) * sc;
                float y1 = (acc[mt][nt][1] + by) * sc;
                float y2 = (acc[mt][nt][2] + bx) * sc;
                float y3 = (acc[mt][nt][3] + by) * sc;
                __nv_bfloat16 h0 = __float2bfloat16(y0), h1 = __float2bfloat16(y1);
                __nv_bfloat16 h2 = __float2bfloat16(y2), h3 = __float2bfloat16(y3);
                *reinterpret_cast<uint32_t*>(Yh + (size_t)r0 * DM + c0) = pack2(h0, h1);
                *reinterpret_cast<uint32_t*>(Yh + (size_t)(r0 + 8) * DM + c0) = pack2(h2, h3);
                *reinterpret_cast<uint32_t*>(Yl + (size_t)r0 * DM + c0) =
                    pack2(__float2bfloat16(y0 - __bfloat162float(h0)),
                          __float2bfloat16(y1 - __bfloat162float(h1)));
                *reinterpret_cast<uint32_t*>(Yl + (size_t)(r0 + 8) * DM + c0) =
                    pack2(__float2bfloat16(y2 - __bfloat162float(h2)),
                          __float2bfloat16(y3 - __bfloat162float(h3)));
            }
        }
    } else {  // mode 2: compact head layout [b,h][key][HD]
        __nv_bfloat16* Yh = p.Yhi[z];
        __nv_bfloat16* Yl = p.Ylo[z];
#pragma unroll
        for (int mt = 0; mt < 4; mt++) {
            int r0 = bm + wm * 64 + mt * 16 + (lane >> 2);
            int key = r0 & (LL - 1);
#pragma unroll
            for (int nt = 0; nt < 4; nt++) {
                int c0 = bn + wn * 32 + nt * 8 + (lane & 3) * 2;
                int hh = c0 >> 6, d = c0 & 63;
                size_t base = ((size_t)(b * NH + hh) * LL + key) * HD + d;
                float bx = bias[c0], by = bias[c0 + 1];
                float y0 = acc[mt][nt][0] + bx;
                float y1 = acc[mt][nt][1] + by;
                float y2 = acc[mt][nt][2] + bx;
                float y3 = acc[mt][nt][3] + by;
                __nv_bfloat16 h0 = __float2bfloat16(y0), h1 = __float2bfloat16(y1);
                __nv_bfloat16 h2 = __float2bfloat16(y2), h3 = __float2bfloat16(y3);
                *reinterpret_cast<uint32_t*>(Yh + base) = pack2(h0, h1);
                *reinterpret_cast<uint32_t*>(Yh + base + 8 * HD) = pack2(h2, h3);
                *reinterpret_cast<uint32_t*>(Yl + base) =
                    pack2(__float2bfloat16(y0 - __bfloat162float(h0)),
                          __float2bfloat16(y1 - __bfloat162float(h1)));
                *reinterpret_cast<uint32_t*>(Yl + base + 8 * HD) =
                    pack2(__float2bfloat16(y2 - __bfloat162float(h2)),
                          __float2bfloat16(y3 - __bfloat162float(h3)));
            }
        }
    }
}

// =================================================================
// V transpose: [b,h][key][HD] bf16 -> [b,h][HD][key] bf16 (hi and lo)
// =================================================================
__global__ __launch_bounds__(256)
void vtrans(const __nv_bfloat16* __restrict__ Vc, const __nv_bfloat16* __restrict__ Vcl,
            const int* __restrict__ nact,
            __nv_bfloat16* __restrict__ Vth, __nv_bfloat16* __restrict__ Vtl)
{
    __shared__ __nv_bfloat16 sh[128 * 72];
    const int it = blockIdx.x, h = blockIdx.y, b = blockIdx.z;
    const int bh = b * NH + h;
    const int na = nact[b];
    const int bound = (na + 63) & ~63;
    const int k0 = it * 128;
    if (k0 >= bound) return;
    const int tid = threadIdx.x;
    const int d = tid >> 2, ks = (tid & 3) * 32;

#pragma unroll
    for (int ps = 0; ps < 2; ps++) {
        const __nv_bfloat16* src = ps ? Vcl : Vc;
        __nv_bfloat16* dst = ps ? Vtl : Vth;
        if (ps) __syncthreads();
        for (int i = tid; i < 128 * 8; i += 256) {
            int row = i >> 3, seg = i & 7;
            *reinterpret_cast<float4*>(&sh[row * 72 + seg * 8]) =
                *reinterpret_cast<const float4*>(src + ((size_t)bh * LL + k0 + row) * HD + seg * 8);
        }
        __syncthreads();
        __nv_bfloat16 buf[32];
#pragma unroll
        for (int j = 0; j < 32; j++) buf[j] = sh[(ks + j) * 72 + d];
        float4* dp = reinterpret_cast<float4*>(dst + ((size_t)bh * HD + d) * LL + k0 + ks);
        const float4* bp = reinterpret_cast<const float4*>(buf);
#pragma unroll
        for (int j = 0; j < 4; j++) dp[j] = bp[j];
    }
}

// =================================================================
// Flash attention, mma.sync + cp.async double-buffered K/V tiles.
// Interleaved P-pack/PV to cut live registers; 2 CTAs/SM target.
// =================================================================
#define FQH 0
#define FQL 18432
#define FSB 36864
#define FSTG 36864
#define FTOT (FSB + 2 * FSTG)  // 110592

__global__ __launch_bounds__(256, 2)
void flash_mma(const __nv_bfloat16* __restrict__ Qhi, const __nv_bfloat16* __restrict__ Qlo,
               const __nv_bfloat16* __restrict__ Kchi, const __nv_bfloat16* __restrict__ Kclo,
               const __nv_bfloat16* __restrict__ Vthi, const __nv_bfloat16* __restrict__ Vtlo,
               const int* __restrict__ nact,
               __nv_bfloat16* __restrict__ Ohi, __nv_bfloat16* __restrict__ Olo)
{
    extern __shared__ char smem[];
    const int qt = blockIdx.x, h = blockIdx.y, b = blockIdx.z;
    const int tid = threadIdx.x, lane = tid & 31, w = tid >> 5;
    const int bh = b * NH + h;
    const int na = nact[b];
    const int ktiles = (na + 63) >> 6;
    const uint32_t su = smem_u32(smem);

    {
        const __nv_bfloat16* qh = Qhi + ((size_t)(b * LL + qt * 128)) * DM + h * HD;
        const __nv_bfloat16* ql = Qlo + ((size_t)(b * LL + qt * 128)) * DM + h * HD;
        for (int idx = tid; idx < 1024; idx += 256) {
            int row = idx >> 3, seg = idx & 7;
            *reinterpret_cast<float4*>(smem + FQH + row * 144 + seg * 16) =
                *reinterpret_cast<const float4*>(qh + (size_t)row * DM + seg * 8);
            *reinterpret_cast<float4*>(smem + FQL + row * 144 + seg * 16) =
                *reinterpret_cast<const float4*>(ql + (size_t)row * DM + seg * 8);
        }
    }

    auto issue = [&](int s, int kt) {
        uint32_t sb = su + FSB + (uint32_t)s * FSTG;
        const __nv_bfloat16* kh = Kchi + ((size_t)bh * LL + kt * 64) * HD;
        const __nv_bfloat16* kl = Kclo + ((size_t)bh * LL + kt * 64) * HD;
        const __nv_bfloat16* vh = Vthi + (size_t)bh * HD * LL + kt * 64;
        const __nv_bfloat16* vl = Vtlo + (size_t)bh * HD * LL + kt * 64;
#pragma unroll
        for (int rep = 0; rep < 2; rep++) {
            int ch = tid + rep * 256;
            int row = ch >> 3, seg = ch & 7;
            uint32_t doff = (uint32_t)(row * 144 + seg * 16);
            CP16(sb + doff,          kh + (size_t)row * HD + seg * 8);
            CP16(sb + 9216 + doff,   kl + (size_t)row * HD + seg * 8);
            CP16(sb + 18432 + doff,  vh + (size_t)row * LL + seg * 8);
            CP16(sb + 27648 + doff,  vl + (size_t)row * LL + seg * 8);
        }
    };

    float m0 = -3.0e38f, m1 = -3.0e38f, l0 = 0.f, l1 = 0.f;
    float oacc[8][4];
#pragma unroll
    for (int nt = 0; nt < 8; nt++)
#pragma unroll
        for (int e = 0; e < 4; e++) oacc[nt][e] = 0.f;

    const uint32_t qaoff = (uint32_t)(((lane & 15) * 72 + (lane >> 4) * 8) * 2);
    const uint32_t boff  = (uint32_t)(((lane & 7) * 72 + ((lane >> 3) & 1) * 8) * 2);
    const uint32_t qrowoff = (uint32_t)(w * 16 * 144);

    issue(0, 0);
    CPCOMMIT();

    for (int kt = 0; kt < ktiles; kt++) {
        CPWAIT0();
        __syncthreads();
        if (kt + 1 < ktiles) { issue((kt + 1) & 1, kt + 1); CPCOMMIT(); }
        const uint32_t sb = su + FSB + (uint32_t)(kt & 1) * FSTG;
        const uint32_t uKH = sb, uKL = sb + 9216, uVH = sb + 18432, uVL = sb + 27648;

        float sacc[8][4];
#pragma unroll
        for (int nt = 0; nt < 8; nt++)
#pragma unroll
            for (int e = 0; e < 4; e++) sacc[nt][e] = 0.f;

#pragma unroll
        for (int ks = 0; ks < 4; ks++) {
            uint32_t ah[4], al[4];
            ldm_x4(ah, su + FQH + qrowoff + qaoff + ks * 32);
            ldm_x4(al, su + FQL + qrowoff + qaoff + ks * 32);
#pragma unroll
            for (int nt = 0; nt < 8; nt++) {
                uint32_t bh2[2], bl2[2];
                ldm_x2(bh2, uKH + nt * 1152 + boff + ks * 32);
                ldm_x2(bl2, uKL + nt * 1152 + boff + ks * 32);
                mma16816(sacc[nt], ah, bh2);
                mma16816(sacc[nt], ah, bl2);
                mma16816(sacc[nt], al, bh2);
            }
        }

        if (kt == ktiles - 1) {
            int jb = kt * 64 + 2 * (lane & 3);
#pragma unroll
            for (int nt = 0; nt < 8; nt++) {
                if (jb + nt * 8     >= na) { sacc[nt][0] = -1e30f; sacc[nt][2] = -1e30f; }
                if (jb + nt * 8 + 1 >= na) { sacc[nt][1] = -1e30f; sacc[nt][3] = -1e30f; }
            }
        }

        float rm0 = -3.0e38f, rm1 = -3.0e38f;
#pragma unroll
        for (int nt = 0; nt < 8; nt++) {
            rm0 = fmaxf(rm0, fmaxf(sacc[nt][0], sacc[nt][1]));
            rm1 = fmaxf(rm1, fmaxf(sacc[nt][2], sacc[nt][3]));
        }
        rm0 = fmaxf(rm0, __shfl_xor_sync(0xffffffffu, rm0, 1));
        rm0 = fmaxf(rm0, __shfl_xor_sync(0xffffffffu, rm0, 2));
        rm1 = fmaxf(rm1, __shfl_xor_sync(0xffffffffu, rm1, 1));
        rm1 = fmaxf(rm1, __shfl_xor_sync(0xffffffffu, rm1, 2));
        float mn0 = fmaxf(m0, rm0), mn1 = fmaxf(m1, rm1);
        float c0 = ex2(m0 - mn0), c1 = ex2(m1 - mn1);
        m0 = mn0; m1 = mn1;

        // scale O accumulators BEFORE PV of this tile
#pragma unroll
        for (int nt = 0; nt < 8; nt++) {
            oacc[nt][0] *= c0; oacc[nt][1] *= c0;
            oacc[nt][2] *= c1; oacc[nt][3] *= c1;
        }

        // interleaved: pack one t-slice of P, immediately do its PV
        float rs0 = 0.f, rs1 = 0.f;
#pragma unroll
        for (int t = 0; t < 4; t++) {
            uint32_t pah4[4], pal4[4];
#pragma unroll
            for (int e = 0; e < 2; e++) {
                int nt = 2 * t + e;
                float p0 = ex2(sacc[nt][0] - mn0);
                float p1 = ex2(sacc[nt][1] - mn0);
                float p2 = ex2(sacc[nt][2] - mn1);
                float p3 = ex2(sacc[nt][3] - mn1);
                rs0 += p0 + p1;
                rs1 += p2 + p3;
                __nv_bfloat16 h0 = __float2bfloat16(p0), h1 = __float2bfloat16(p1);
                __nv_bfloat16 h2 = __float2bfloat16(p2), h3 = __float2bfloat16(p3);
                pah4[2 * e]     = pack2(h0, h1);
                pah4[2 * e + 1] = pack2(h2, h3);
                pal4[2 * e]     = pack2(__float2bfloat16(p0 - __bfloat162float(h0)),
                                        __float2bfloat16(p1 - __bfloat162float(h1)));
                pal4[2 * e + 1] = pack2(__float2bfloat16(p2 - __bfloat162float(h2)),
                                        __float2bfloat16(p3 - __bfloat162float(h3)));
            }
#pragma unroll
            for (int nt = 0; nt < 8; nt++) {
                uint32_t bvh[2], bvl[2];
                ldm_x2(bvh, uVH + nt * 1152 + boff + t * 32);
                ldm_x2(bvl, uVL + nt * 1152 + boff + t * 32);
                mma16816(oacc[nt], pah4, bvh);
                mma16816(oacc[nt], pah4, bvl);
                mma16816(oacc[nt], pal4, bvh);
            }
        }
        rs0 += __shfl_xor_sync(0xffffffffu, rs0, 1);
        rs0 += __shfl_xor_sync(0xffffffffu, rs0, 2);
        rs1 += __shfl_xor_sync(0xffffffffu, rs1, 1);
        rs1 += __shfl_xor_sync(0xffffffffu, rs1, 2);
        l0 = l0 * c0 + rs0;
        l1 = l1 * c1 + rs1;
    }

    float i0 = 1.f / l0, i1 = 1.f / l1;
    int r = lane >> 2;
    size_t row0 = (size_t)b * LL + qt * 128 + w * 16 + r;
    int cc0 = h * HD + 2 * (lane & 3);
#pragma unroll
    for (int nt = 0; nt < 8; nt++) {
        int cc = cc0 + nt * 8;
        float y0 = oacc[nt][0] * i0, y1 = oacc[nt][1] * i0;
        float y2 = oacc[nt][2] * i1, y3 = oacc[nt][3] * i1;
        __nv_bfloat16 h0 = __float2bfloat16(y0), h1 = __float2bfloat16(y1);
        __nv_bfloat16 h2 = __float2bfloat16(y2), h3 = __float2bfloat16(y3);
        *reinterpret_cast<uint32_t*>(Ohi + row0 * DM + cc) = pack2(h0, h1);
        *reinterpret_cast<uint32_t*>(Ohi + (row0 + 8) * DM + cc) = pack2(h2, h3);
        *reinterpret_cast<uint32_t*>(Olo + row0 * DM + cc) =
            pack2(__float2bfloat16(y0 - __bfloat162float(h0)),
                  __float2bfloat16(y1 - __bfloat162float(h1)));
        *reinterpret_cast<uint32_t*>(Olo + (row0 + 8) * DM + cc) =
            pack2(__float2bfloat16(y2 - __bfloat162float(h2)),
                  __float2bfloat16(y3 - __bfloat162float(h3)));
    }
}

// =================================================================
// launch
// =================================================================
extern "C" void kernel_launch(void* const* d_in, const int* in_sizes, int n_in,
                              void* d_out, int out_size)
{
    const float* q    = (const float*)d_in[0];
    const float* k    = (const float*)d_in[1];
    const float* v    = (const float*)d_in[2];
    const int*   mask = (const int*)d_in[3];
    const float* Wq   = (const float*)d_in[4];
    const float* bq   = (const float*)d_in[5];
    const float* Wk   = (const float*)d_in[6];
    const float* bk   = (const float*)d_in[7];
    const float* Wv   = (const float*)d_in[8];
    const float* bv   = (const float*)d_in[9];
    const float* Wo   = (const float*)d_in[10];
    const float* bo   = (const float*)d_in[11];

    __nv_bfloat16 *x0h, *x0l, *x1h, *x1l, *x2h, *x2l;
    __nv_bfloat16 *w0h, *w0l, *w1h, *w1l, *w2h, *w2l, *w3h, *w3l;
    __nv_bfloat16 *qhi, *qlo, *kchi, *kclo, *vchi, *vclo, *vthi, *vtlo, *ahi, *alo;
    int *cidx, *nact;
    cudaGetSymbolAddress((void**)&x0h, g_x0hi); cudaGetSymbolAddress((void**)&x0l, g_x0lo);
    cudaGetSymbolAddress((void**)&x1h, g_x1hi); cudaGetSymbolAddress((void**)&x1l, g_x1lo);
    cudaGetSymbolAddress((void**)&x2h, g_x2hi); cudaGetSymbolAddress((void**)&x2l, g_x2lo);
    cudaGetSymbolAddress((void**)&w0h, g_w0hi); cudaGetSymbolAddress((void**)&w0l, g_w0lo);
    cudaGetSymbolAddress((void**)&w1h, g_w1hi); cudaGetSymbolAddress((void**)&w1l, g_w1lo);
    cudaGetSymbolAddress((void**)&w2h, g_w2hi); cudaGetSymbolAddress((void**)&w2l, g_w2lo);
    cudaGetSymbolAddress((void**)&w3h, g_w3hi); cudaGetSymbolAddress((void**)&w3l, g_w3lo);
    cudaGetSymbolAddress((void**)&qhi, g_qhi);  cudaGetSymbolAddress((void**)&qlo, g_qlo);
    cudaGetSymbolAddress((void**)&kchi, g_kchi); cudaGetSymbolAddress((void**)&kclo, g_kclo);
    cudaGetSymbolAddress((void**)&vchi, g_vchi); cudaGetSymbolAddress((void**)&vclo, g_vclo);
    cudaGetSymbolAddress((void**)&vthi, g_vthi); cudaGetSymbolAddress((void**)&vtlo, g_vtlo);
    cudaGetSymbolAddress((void**)&ahi, g_ahi);  cudaGetSymbolAddress((void**)&alo, g_alo);
    cudaGetSymbolAddress((void**)&cidx, g_cidx);
    cudaGetSymbolAddress((void**)&nact, g_nact);

    cudaFuncSetAttribute(gemm_mma2, cudaFuncAttributeMaxDynamicSharedMemorySize, 2 * GSTG);
    cudaFuncSetAttribute(flash_mma, cudaFuncAttributeMaxDynamicSharedMemorySize, FTOT);

    const int NX = ML * DM;
    const int NW = DM * DM;

    compact_mask<<<BB, 256>>>(mask, cidx, nact);

    // fused splits: 3 activations + 4 weights in one launch
    SP sp{};
    sp.src[0] = q;  sp.hi[0] = x0h; sp.lo[0] = x0l; sp.n[0] = NX;
    sp.src[1] = k;  sp.hi[1] = x1h; sp.lo[1] = x1l; sp.n[1] = NX;
    sp.src[2] = v;  sp.hi[2] = x2h; sp.lo[2] = x2l; sp.n[2] = NX;
    sp.src[3] = Wq; sp.hi[3] = w0h; sp.lo[3] = w0l; sp.n[3] = NW;
    sp.src[4] = Wk; sp.hi[4] = w1h; sp.lo[4] = w1l; sp.n[4] = NW;
    sp.src[5] = Wv; sp.hi[5] = w2h; sp.lo[5] = w2l; sp.n[5] = NW;
    sp.src[6] = Wo; sp.hi[6] = w3h; sp.lo[6] = w3l; sp.n[6] = NW;
    split_all<<<dim3(1024, 7), 256>>>(sp);

    GP p{};
    p.cidx = cidx; p.nact = nact;
    // z=0: Q projection -> scaled bf16 split, full rows
    p.Ahi[0] = x0h; p.Alo[0] = x0l; p.Bhi[0] = w0h; p.Blo[0] = w0l;
    p.bias[0] = bq; p.Yhi[0] = qhi; p.Ylo[0] = qlo;
    p.scale[0] = 0.18033688011112042f;  // 0.125 * log2(e)
    p.mode[0] = 1; p.gather[0] = 0;
    // z=1: K projection -> compacted rows, compact head layout
    p.Ahi[1] = x1h; p.Alo[1] = x1l; p.Bhi[1] = w1h; p.Blo[1] = w1l;
    p.bias[1] = bk; p.Yhi[1] = kchi; p.Ylo[1] = kclo;
    p.mode[1] = 2; p.gather[1] = 1;
    // z=2: V projection -> compacted rows, compact head layout
    p.Ahi[2] = x2h; p.Alo[2] = x2l; p.Bhi[2] = w2h; p.Blo[2] = w2l;
    p.bias[2] = bv; p.Yhi[2] = vchi; p.Ylo[2] = vclo;
    p.mode[2] = 2; p.gather[2] = 1;
    gemm_mma2<<<dim3(DM / 128, ML / 128, 3), 256, 2 * GSTG>>>(p);

    vtrans<<<dim3(LL / 128, NH, BB), 256>>>(vchi, vclo, nact, vthi, vtlo);

    flash_mma<<<dim3(LL / 128, NH, BB), 256, FTOT>>>(qhi, qlo, kchi, kclo, vthi, vtlo,
                                                     nact, ahi, alo);

    GP p2{};
    p2.cidx = cidx; p2.nact = nact;
    p2.Ahi[0] = ahi; p2.Alo[0] = alo; p2.Bhi[0] = w3h; p2.Blo[0] = w3l;
    p2.bias[0] = bo; p2.Yf[0] = (float*)d_out; p2.mode[0] = 0; p2.gather[0] = 0;
    gemm_mma2<<<dim3(DM / 128, ML / 128, 1), 256, 2 * GSTG>>>(p2);
}

// round 16
// speedup vs baseline: 1.0057x; 1.0057x over previous
#include <cuda_runtime.h>
#include <cuda_bf16.h>
#include <cstdint>

#define DM 1024
#define NH 16
#define HD 64
#define BB 2
#define LL 2048
#define ML (BB * LL)  // 4096 total rows

// ---------------- scratch (no allocation allowed) ----------------
__device__ __nv_bfloat16 g_x0hi[ML * DM], g_x0lo[ML * DM];
__device__ __nv_bfloat16 g_x1hi[ML * DM], g_x1lo[ML * DM];
__device__ __nv_bfloat16 g_x2hi[ML * DM], g_x2lo[ML * DM];
__device__ __nv_bfloat16 g_w0hi[DM * DM], g_w0lo[DM * DM];
__device__ __nv_bfloat16 g_w1hi[DM * DM], g_w1lo[DM * DM];
__device__ __nv_bfloat16 g_w2hi[DM * DM], g_w2lo[DM * DM];
__device__ __nv_bfloat16 g_w3hi[DM * DM], g_w3lo[DM * DM];
__device__ __nv_bfloat16 g_qhi[ML * DM], g_qlo[ML * DM];
__device__ __nv_bfloat16 g_kchi[BB * NH * LL * HD], g_kclo[BB * NH * LL * HD];
__device__ __nv_bfloat16 g_vchi[BB * NH * LL * HD], g_vclo[BB * NH * LL * HD];
__device__ __nv_bfloat16 g_vthi[BB * NH * HD * LL], g_vtlo[BB * NH * HD * LL];
__device__ __nv_bfloat16 g_ahi[ML * DM], g_alo[ML * DM];  // flash output (split)
__device__ int g_cidx[BB * LL];
__device__ int g_nact[BB];

// ================= helpers (base compute_103 PTX only) ==========
__device__ __forceinline__ uint32_t smem_u32(const void* p) {
    uint32_t a;
    asm("{ .reg .u64 t; cvta.to.shared.u64 t, %1; cvt.u32.u64 %0, t; }" : "=r"(a) : "l"(p));
    return a;
}
__device__ __forceinline__ void ldm_x4(uint32_t* r, uint32_t addr) {
    asm volatile("ldmatrix.sync.aligned.m8n8.x4.shared.b16 {%0,%1,%2,%3}, [%4];"
                 : "=r"(r[0]), "=r"(r[1]), "=r"(r[2]), "=r"(r[3]) : "r"(addr));
}
__device__ __forceinline__ void ldm_x2(uint32_t* r, uint32_t addr) {
    asm volatile("ldmatrix.sync.aligned.m8n8.x2.shared.b16 {%0,%1}, [%2];"
                 : "=r"(r[0]), "=r"(r[1]) : "r"(addr));
}
__device__ __forceinline__ void mma16816(float* c, const uint32_t* a, const uint32_t* b) {
    asm volatile("mma.sync.aligned.m16n8k16.row.col.f32.bf16.bf16.f32 "
                 "{%0,%1,%2,%3}, {%4,%5,%6,%7}, {%8,%9}, {%0,%1,%2,%3};"
                 : "+f"(c[0]), "+f"(c[1]), "+f"(c[2]), "+f"(c[3])
                 : "r"(a[0]), "r"(a[1]), "r"(a[2]), "r"(a[3]), "r"(b[0]), "r"(b[1]));
}
__device__ __forceinline__ float ex2(float x) {
    float y;
    asm("ex2.approx.ftz.f32 %0, %1;" : "=f"(y) : "f"(x));
    return y;
}
__device__ __forceinline__ uint32_t pack2(__nv_bfloat16 a, __nv_bfloat16 b) {
    __nv_bfloat162 t = __halves2bfloat162(a, b);
    return *reinterpret_cast<uint32_t*>(&t);
}
#define CP16(d, s) asm volatile("cp.async.cg.shared.global [%0], [%1], 16;" :: "r"(d), "l"(s))
#define CPCOMMIT() asm volatile("cp.async.commit_group;" ::: "memory")
#define CPWAIT0()  asm volatile("cp.async.wait_group 0;" ::: "memory")

// =================================================================
// fused split: all 7 fp32 arrays -> bf16 hi/lo in one launch
// =================================================================
struct SP {
    const float* src[7];
    __nv_bfloat16* hi[7];
    __nv_bfloat16* lo[7];
    int n[7];
};

__global__ __launch_bounds__(256)
void split_all(SP sp)
{
    const int s = blockIdx.y;
    const float* __restrict__ x = sp.src[s];
    __nv_bfloat16* __restrict__ hi = sp.hi[s];
    __nv_bfloat16* __restrict__ lo = sp.lo[s];
    const int n = sp.n[s];
    const int stride = gridDim.x * 1024;
    for (int i = (blockIdx.x * 256 + threadIdx.x) * 4; i < n; i += stride) {
        float4 f = *reinterpret_cast<const float4*>(x + i);
        __nv_bfloat16 h0 = __float2bfloat16(f.x);
        __nv_bfloat16 h1 = __float2bfloat16(f.y);
        __nv_bfloat16 h2 = __float2bfloat16(f.z);
        __nv_bfloat16 h3 = __float2bfloat16(f.w);
        *reinterpret_cast<uint32_t*>(hi + i)     = pack2(h0, h1);
        *reinterpret_cast<uint32_t*>(hi + i + 2) = pack2(h2, h3);
        *reinterpret_cast<uint32_t*>(lo + i) =
            pack2(__float2bfloat16(f.x - __bfloat162float(h0)),
                  __float2bfloat16(f.y - __bfloat162float(h1)));
        *reinterpret_cast<uint32_t*>(lo + i + 2) =
            pack2(__float2bfloat16(f.z - __bfloat162float(h2)),
                  __float2bfloat16(f.w - __bfloat162float(h3)));
    }
}

// =================================================================
// mask compaction (deterministic, parallel scan)
// =================================================================
__global__ __launch_bounds__(256)
void compact_mask(const int* __restrict__ mask, int* __restrict__ cidx,
                  int* __restrict__ nact)
{
    int b = blockIdx.x, tid = threadIdx.x;
    __shared__ int ws[256];
    const int* mb = mask + b * LL;
    int base = tid * 8;
    int loc[8];
    int cnt = 0;
#pragma unroll
    for (int i = 0; i < 8; i++) { loc[i] = cnt; cnt += (mb[base + i] == 0); }
    ws[tid] = cnt;
    __syncthreads();
    // Hillis-Steele inclusive scan
#pragma unroll
    for (int o = 1; o < 256; o <<= 1) {
        int add = (tid >= o) ? ws[tid - o] : 0;
        __syncthreads();
        ws[tid] += add;
        __syncthreads();
    }
    if (tid == 255) nact[b] = ws[255];
    int off = ws[tid] - cnt;  // exclusive
#pragma unroll
    for (int i = 0; i < 8; i++)
        if (mb[base + i] == 0) cidx[b * LL + off + loc[i]] = base + i;
}

// =================================================================
// cp.async double-buffered GEMM, batched over z.
// =================================================================
#define LDK 40
#define GSTG 40960

struct GP {
    const __nv_bfloat16 *Ahi[3], *Alo[3], *Bhi[3], *Blo[3];
    const float* bias[3];
    float* Yf[3];
    __nv_bfloat16 *Yhi[3], *Ylo[3];
    float scale[3];
    int mode[3];
    int gather[3];
    const int* cidx;
    const int* nact;
};

__global__ __launch_bounds__(256, 2)
void gemm_mma2(GP p)
{
    extern __shared__ char smem[];
    __shared__ int sidx[128];
    const int z = blockIdx.z;
    const __nv_bfloat16* __restrict__ Ahi = p.Ahi[z];
    const __nv_bfloat16* __restrict__ Alo = p.Alo[z];
    const __nv_bfloat16* __restrict__ Bhi = p.Bhi[z];
    const __nv_bfloat16* __restrict__ Blo = p.Blo[z];
    const float* __restrict__ bias = p.bias[z];

    const int tid = threadIdx.x, lane = tid & 31, wid = tid >> 5;
    const int wm = wid & 1, wn = wid >> 1;
    const int bm = blockIdx.y * 128, bn = blockIdx.x * 128;
    const int gflag = p.gather[z];
    const int b = bm >> 11;  // batch (LL=2048)
    const uint32_t su = smem_u32(smem);

    if (gflag) {
        int na = p.nact[b];
        int bound = (na + 63) & ~63;
        int gi0 = bm & (LL - 1);
        if (gi0 >= bound) return;
        if (tid < 128) {
            int gi = gi0 + tid;
            int gcl = gi < na ? gi : na - 1;
            sidx[tid] = p.cidx[b * LL + gcl];
        }
        __syncthreads();
    }

    float acc[4][4][4];
#pragma unroll
    for (int mt = 0; mt < 4; mt++)
#pragma unroll
        for (int nt = 0; nt < 4; nt++)
#pragma unroll
            for (int e = 0; e < 4; e++) acc[mt][nt][e] = 0.f;

    const uint32_t aoff = (uint32_t)(((lane & 15) * LDK + (lane >> 4) * 8) * 2);
    const uint32_t boff = (uint32_t)(((lane & 7) * LDK + ((lane >> 3) & 1) * 8) * 2);

    auto issue = [&](int s, int c) {
        uint32_t sb = su + (uint32_t)s * GSTG;
        int k0 = c * 32;
#pragma unroll
        for (int rep = 0; rep < 2; rep++) {
            int ch = tid + rep * 256;              // 0..511: 128 rows x 4 segs (64B/row)
            int row = ch >> 2, seg = ch & 3;
            uint32_t doff = (uint32_t)(row * 80 + seg * 16);
            size_t arow = gflag ? (size_t)(b * LL + sidx[row]) : (size_t)(bm + row);
            size_t goA = arow * DM + k0 + seg * 8;
            size_t goB = (size_t)(bn + row) * DM + k0 + seg * 8;
            CP16(sb + doff,         Ahi + goA);
            CP16(sb + 10240 + doff, Alo + goA);
            CP16(sb + 20480 + doff, Bhi + goB);
            CP16(sb + 30720 + doff, Blo + goB);
        }
    };

    issue(0, 0);
    CPCOMMIT();

    for (int c = 0; c < 32; c++) {
        CPWAIT0();
        __syncthreads();
        if (c + 1 < 32) { issue((c + 1) & 1, c + 1); CPCOMMIT(); }
        const uint32_t sb = su + (uint32_t)(c & 1) * GSTG;
        const uint32_t uAh = sb, uAl = sb + 10240, uBh = sb + 20480, uBl = sb + 30720;
#pragma unroll
        for (int ks = 0; ks < 2; ks++) {
            const uint32_t kb = (uint32_t)(ks * 32);
            uint32_t ah[4][4], al[4][4], bh[4][2], bl[4][2];
#pragma unroll
            for (int mt = 0; mt < 4; mt++) {
                uint32_t r = (uint32_t)((wm * 64 + mt * 16) * LDK * 2) + aoff + kb;
                ldm_x4(ah[mt], uAh + r);
                ldm_x4(al[mt], uAl + r);
            }
#pragma unroll
            for (int nt = 0; nt < 4; nt++) {
                uint32_t r = (uint32_t)((wn * 32 + nt * 8) * LDK * 2) + boff + kb;
                ldm_x2(bh[nt], uBh + r);
                ldm_x2(bl[nt], uBl + r);
            }
#pragma unroll
            for (int mt = 0; mt < 4; mt++)
#pragma unroll
                for (int nt = 0; nt < 4; nt++) {
                    mma16816(acc[mt][nt], ah[mt], bh[nt]);
                    mma16816(acc[mt][nt], ah[mt], bl[nt]);
                    mma16816(acc[mt][nt], al[mt], bh[nt]);
                }
        }
    }

    const int mode = p.mode[z];
    if (mode == 0) {
        float* Y = p.Yf[z];
#pragma unroll
        for (int mt = 0; mt < 4; mt++) {
            int r0 = bm + wm * 64 + mt * 16 + (lane >> 2);
#pragma unroll
            for (int nt = 0; nt < 4; nt++) {
                int c0 = bn + wn * 32 + nt * 8 + (lane & 3) * 2;
                float bx = bias[c0], by = bias[c0 + 1];
                *reinterpret_cast<float2*>(Y + (size_t)r0 * DM + c0) =
                    make_float2(acc[mt][nt][0] + bx, acc[mt][nt][1] + by);
                *reinterpret_cast<float2*>(Y + (size_t)(r0 + 8) * DM + c0) =
                    make_float2(acc[mt][nt][2] + bx, acc[mt][nt][3] + by);
            }
        }
    } else if (mode == 1) {
        __nv_bfloat16* Yh = p.Yhi[z];
        __nv_bfloat16* Yl = p.Ylo[z];
        const float sc = p.scale[z];
#pragma unroll
        for (int mt = 0; mt < 4; mt++) {
            int r0 = bm + wm * 64 + mt * 16 + (lane >> 2);
#pragma unroll
            for (int nt = 0; nt < 4; nt++) {
                int c0 = bn + wn * 32 + nt * 8 + (lane & 3) * 2;
                float bx = bias[c0], by = bias[c0 + 1];
                float y0 = (acc[mt][nt][0] + bx) * sc;
                float y1 = (acc[mt][nt][1] + by) * sc;
                float y2 = (acc[mt][nt][2] + bx) * sc;
                float y3 = (acc[mt][nt][3] + by) * sc;
                __nv_bfloat16 h0 = __float2bfloat16(y0), h1 = __float2bfloat16(y1);
                __nv_bfloat16 h2 = __float2bfloat16(y2), h3 = __float2bfloat16(y3);
                *reinterpret_cast<uint32_t*>(Yh + (size_t)r0 * DM + c0) = pack2(h0, h1);
                *reinterpret_cast<uint32_t*>(Yh + (size_t)(r0 + 8) * DM + c0) = pack2(h2, h3);
                *reinterpret_cast<uint32_t*>(Yl + (size_t)r0 * DM + c0) =
                    pack2(__float2bfloat16(y0 - __bfloat162float(h0)),
                          __float2bfloat16(y1 - __bfloat162float(h1)));
                *reinterpret_cast<uint32_t*>(Yl + (size_t)(r0 + 8) * DM + c0) =
                    pack2(__float2bfloat16(y2 - __bfloat162float(h2)),
                          __float2bfloat16(y3 - __bfloat162float(h3)));
            }
        }
    } else {  // mode 2: compact head layout [b,h][key][HD]
        __nv_bfloat16* Yh = p.Yhi[z];
        __nv_bfloat16* Yl = p.Ylo[z];
#pragma unroll
        for (int mt = 0; mt < 4; mt++) {
            int r0 = bm + wm * 64 + mt * 16 + (lane >> 2);
            int key = r0 & (LL - 1);
#pragma unroll
            for (int nt = 0; nt < 4; nt++) {
                int c0 = bn + wn * 32 + nt * 8 + (lane & 3) * 2;
                int hh = c0 >> 6, d = c0 & 63;
                size_t base = ((size_t)(b * NH + hh) * LL + key) * HD + d;
                float bx = bias[c0], by = bias[c0 + 1];
                float y0 = acc[mt][nt][0] + bx;
                float y1 = acc[mt][nt][1] + by;
                float y2 = acc[mt][nt][2] + bx;
                float y3 = acc[mt][nt][3] + by;
                __nv_bfloat16 h0 = __float2bfloat16(y0), h1 = __float2bfloat16(y1);
                __nv_bfloat16 h2 = __float2bfloat16(y2), h3 = __float2bfloat16(y3);
                *reinterpret_cast<uint32_t*>(Yh + base) = pack2(h0, h1);
                *reinterpret_cast<uint32_t*>(Yh + base + 8 * HD) = pack2(h2, h3);
                *reinterpret_cast<uint32_t*>(Yl + base) =
                    pack2(__float2bfloat16(y0 - __bfloat162float(h0)),
                          __float2bfloat16(y1 - __bfloat162float(h1)));
                *reinterpret_cast<uint32_t*>(Yl + base + 8 * HD) =
                    pack2(__float2bfloat16(y2 - __bfloat162float(h2)),
                          __float2bfloat16(y3 - __bfloat162float(h3)));
            }
        }
    }
}

// =================================================================
// V transpose: hi and lo processed concurrently (one barrier)
// =================================================================
__global__ __launch_bounds__(256)
void vtrans(const __nv_bfloat16* __restrict__ Vc, const __nv_bfloat16* __restrict__ Vcl,
            const int* __restrict__ nact,
            __nv_bfloat16* __restrict__ Vth, __nv_bfloat16* __restrict__ Vtl)
{
    __shared__ __nv_bfloat16 sh[128 * 72];
    __shared__ __nv_bfloat16 sl[128 * 72];
    const int it = blockIdx.x, h = blockIdx.y, b = blockIdx.z;
    const int bh = b * NH + h;
    const int na = nact[b];
    const int bound = (na + 63) & ~63;
    const int k0 = it * 128;
    if (k0 >= bound) return;
    const int tid = threadIdx.x;
    const int d = tid >> 2, ks = (tid & 3) * 32;

    for (int i = tid; i < 128 * 8; i += 256) {
        int row = i >> 3, seg = i & 7;
        size_t g = ((size_t)bh * LL + k0 + row) * HD + seg * 8;
        *reinterpret_cast<float4*>(&sh[row * 72 + seg * 8]) =
            *reinterpret_cast<const float4*>(Vc + g);
        *reinterpret_cast<float4*>(&sl[row * 72 + seg * 8]) =
            *reinterpret_cast<const float4*>(Vcl + g);
    }
    __syncthreads();
    __nv_bfloat16 bufh[32], bufl[32];
#pragma unroll
    for (int j = 0; j < 32; j++) {
        bufh[j] = sh[(ks + j) * 72 + d];
        bufl[j] = sl[(ks + j) * 72 + d];
    }
    size_t o = ((size_t)bh * HD + d) * LL + k0 + ks;
    float4* dph = reinterpret_cast<float4*>(Vth + o);
    float4* dpl = reinterpret_cast<float4*>(Vtl + o);
    const float4* bph = reinterpret_cast<const float4*>(bufh);
    const float4* bpl = reinterpret_cast<const float4*>(bufl);
#pragma unroll
    for (int j = 0; j < 4; j++) { dph[j] = bph[j]; dpl[j] = bpl[j]; }
}

// =================================================================
// Flash attention, mma.sync + cp.async double-buffered K/V tiles.
// Interleaved P-pack/PV; NO occupancy cap (R12 cap caused spills).
// =================================================================
#define FQH 0
#define FQL 18432
#define FSB 36864
#define FSTG 36864
#define FTOT (FSB + 2 * FSTG)  // 110592

__global__ __launch_bounds__(256)
void flash_mma(const __nv_bfloat16* __restrict__ Qhi, const __nv_bfloat16* __restrict__ Qlo,
               const __nv_bfloat16* __restrict__ Kchi, const __nv_bfloat16* __restrict__ Kclo,
               const __nv_bfloat16* __restrict__ Vthi, const __nv_bfloat16* __restrict__ Vtlo,
               const int* __restrict__ nact,
               __nv_bfloat16* __restrict__ Ohi, __nv_bfloat16* __restrict__ Olo)
{
    extern __shared__ char smem[];
    const int qt = blockIdx.x, h = blockIdx.y, b = blockIdx.z;
    const int tid = threadIdx.x, lane = tid & 31, w = tid >> 5;
    const int bh = b * NH + h;
    const int na = nact[b];
    const int ktiles = (na + 63) >> 6;
    const uint32_t su = smem_u32(smem);

    {
        const __nv_bfloat16* qh = Qhi + ((size_t)(b * LL + qt * 128)) * DM + h * HD;
        const __nv_bfloat16* ql = Qlo + ((size_t)(b * LL + qt * 128)) * DM + h * HD;
        for (int idx = tid; idx < 1024; idx += 256) {
            int row = idx >> 3, seg = idx & 7;
            *reinterpret_cast<float4*>(smem + FQH + row * 144 + seg * 16) =
                *reinterpret_cast<const float4*>(qh + (size_t)row * DM + seg * 8);
            *reinterpret_cast<float4*>(smem + FQL + row * 144 + seg * 16) =
                *reinterpret_cast<const float4*>(ql + (size_t)row * DM + seg * 8);
        }
    }

    auto issue = [&](int s, int kt) {
        uint32_t sb = su + FSB + (uint32_t)s * FSTG;
        const __nv_bfloat16* kh = Kchi + ((size_t)bh * LL + kt * 64) * HD;
        const __nv_bfloat16* kl = Kclo + ((size_t)bh * LL + kt * 64) * HD;
        const __nv_bfloat16* vh = Vthi + (size_t)bh * HD * LL + kt * 64;
        const __nv_bfloat16* vl = Vtlo + (size_t)bh * HD * LL + kt * 64;
#pragma unroll
        for (int rep = 0; rep < 2; rep++) {
            int ch = tid + rep * 256;
            int row = ch >> 3, seg = ch & 7;
            uint32_t doff = (uint32_t)(row * 144 + seg * 16);
            CP16(sb + doff,          kh + (size_t)row * HD + seg * 8);
            CP16(sb + 9216 + doff,   kl + (size_t)row * HD + seg * 8);
            CP16(sb + 18432 + doff,  vh + (size_t)row * LL + seg * 8);
            CP16(sb + 27648 + doff,  vl + (size_t)row * LL + seg * 8);
        }
    };

    float m0 = -3.0e38f, m1 = -3.0e38f, l0 = 0.f, l1 = 0.f;
    float oacc[8][4];
#pragma unroll
    for (int nt = 0; nt < 8; nt++)
#pragma unroll
        for (int e = 0; e < 4; e++) oacc[nt][e] = 0.f;

    const uint32_t qaoff = (uint32_t)(((lane & 15) * 72 + (lane >> 4) * 8) * 2);
    const uint32_t boff  = (uint32_t)(((lane & 7) * 72 + ((lane >> 3) & 1) * 8) * 2);
    const uint32_t qrowoff = (uint32_t)(w * 16 * 144);

    issue(0, 0);
    CPCOMMIT();

    for (int kt = 0; kt < ktiles; kt++) {
        CPWAIT0();
        __syncthreads();
        if (kt + 1 < ktiles) { issue((kt + 1) & 1, kt + 1); CPCOMMIT(); }
        const uint32_t sb = su + FSB + (uint32_t)(kt & 1) * FSTG;
        const uint32_t uKH = sb, uKL = sb + 9216, uVH = sb + 18432, uVL = sb + 27648;

        float sacc[8][4];
#pragma unroll
        for (int nt = 0; nt < 8; nt++)
#pragma unroll
            for (int e = 0; e < 4; e++) sacc[nt][e] = 0.f;

#pragma unroll
        for (int ks = 0; ks < 4; ks++) {
            uint32_t ah[4], al[4];
            ldm_x4(ah, su + FQH + qrowoff + qaoff + ks * 32);
            ldm_x4(al, su + FQL + qrowoff + qaoff + ks * 32);
#pragma unroll
            for (int nt = 0; nt < 8; nt++) {
                uint32_t bh2[2], bl2[2];
                ldm_x2(bh2, uKH + nt * 1152 + boff + ks * 32);
                ldm_x2(bl2, uKL + nt * 1152 + boff + ks * 32);
                mma16816(sacc[nt], ah, bh2);
                mma16816(sacc[nt], ah, bl2);
                mma16816(sacc[nt], al, bh2);
            }
        }

        if (kt == ktiles - 1) {
            int jb = kt * 64 + 2 * (lane & 3);
#pragma unroll
            for (int nt = 0; nt < 8; nt++) {
                if (jb + nt * 8     >= na) { sacc[nt][0] = -1e30f; sacc[nt][2] = -1e30f; }
                if (jb + nt * 8 + 1 >= na) { sacc[nt][1] = -1e30f; sacc[nt][3] = -1e30f; }
            }
        }

        float rm0 = -3.0e38f, rm1 = -3.0e38f;
#pragma unroll
        for (int nt = 0; nt < 8; nt++) {
            rm0 = fmaxf(rm0, fmaxf(sacc[nt][0], sacc[nt][1]));
            rm1 = fmaxf(rm1, fmaxf(sacc[nt][2], sacc[nt][3]));
        }
        rm0 = fmaxf(rm0, __shfl_xor_sync(0xffffffffu, rm0, 1));
        rm0 = fmaxf(rm0, __shfl_xor_sync(0xffffffffu, rm0, 2));
        rm1 = fmaxf(rm1, __shfl_xor_sync(0xffffffffu, rm1, 1));
        rm1 = fmaxf(rm1, __shfl_xor_sync(0xffffffffu, rm1, 2));
        float mn0 = fmaxf(m0, rm0), mn1 = fmaxf(m1, rm1);
        float c0 = ex2(m0 - mn0), c1 = ex2(m1 - mn1);
        m0 = mn0; m1 = mn1;

#pragma unroll
        for (int nt = 0; nt < 8; nt++) {
            oacc[nt][0] *= c0; oacc[nt][1] *= c0;
            oacc[nt][2] *= c1; oacc[nt][3] *= c1;
        }

        float rs0 = 0.f, rs1 = 0.f;
#pragma unroll
        for (int t = 0; t < 4; t++) {
            uint32_t pah4[4], pal4[4];
#pragma unroll
            for (int e = 0; e < 2; e++) {
                int nt = 2 * t + e;
                float p0 = ex2(sacc[nt][0] - mn0);
                float p1 = ex2(sacc[nt][1] - mn0);
                float p2 = ex2(sacc[nt][2] - mn1);
                float p3 = ex2(sacc[nt][3] - mn1);
                rs0 += p0 + p1;
                rs1 += p2 + p3;
                __nv_bfloat16 h0 = __float2bfloat16(p0), h1 = __float2bfloat16(p1);
                __nv_bfloat16 h2 = __float2bfloat16(p2), h3 = __float2bfloat16(p3);
                pah4[2 * e]     = pack2(h0, h1);
                pah4[2 * e + 1] = pack2(h2, h3);
                pal4[2 * e]     = pack2(__float2bfloat16(p0 - __bfloat162float(h0)),
                                        __float2bfloat16(p1 - __bfloat162float(h1)));
                pal4[2 * e + 1] = pack2(__float2bfloat16(p2 - __bfloat162float(h2)),
                                        __float2bfloat16(p3 - __bfloat162float(h3)));
            }
#pragma unroll
            for (int nt = 0; nt < 8; nt++) {
                uint32_t bvh[2], bvl[2];
                ldm_x2(bvh, uVH + nt * 1152 + boff + t * 32);
                ldm_x2(bvl, uVL + nt * 1152 + boff + t * 32);
                mma16816(oacc[nt], pah4, bvh);
                mma16816(oacc[nt], pah4, bvl);
                mma16816(oacc[nt], pal4, bvh);
            }
        }
        rs0 += __shfl_xor_sync(0xffffffffu, rs0, 1);
        rs0 += __shfl_xor_sync(0xffffffffu, rs0, 2);
        rs1 += __shfl_xor_sync(0xffffffffu, rs1, 1);
        rs1 += __shfl_xor_sync(0xffffffffu, rs1, 2);
        l0 = l0 * c0 + rs0;
        l1 = l1 * c1 + rs1;
    }

    float i0 = 1.f / l0, i1 = 1.f / l1;
    int r = lane >> 2;
    size_t row0 = (size_t)b * LL + qt * 128 + w * 16 + r;
    int cc0 = h * HD + 2 * (lane & 3);
#pragma unroll
    for (int nt = 0; nt < 8; nt++) {
        int cc = cc0 + nt * 8;
        float y0 = oacc[nt][0] * i0, y1 = oacc[nt][1] * i0;
        float y2 = oacc[nt][2] * i1, y3 = oacc[nt][3] * i1;
        __nv_bfloat16 h0 = __float2bfloat16(y0), h1 = __float2bfloat16(y1);
        __nv_bfloat16 h2 = __float2bfloat16(y2), h3 = __float2bfloat16(y3);
        *reinterpret_cast<uint32_t*>(Ohi + row0 * DM + cc) = pack2(h0, h1);
        *reinterpret_cast<uint32_t*>(Ohi + (row0 + 8) * DM + cc) = pack2(h2, h3);
        *reinterpret_cast<uint32_t*>(Olo + row0 * DM + cc) =
            pack2(__float2bfloat16(y0 - __bfloat162float(h0)),
                  __float2bfloat16(y1 - __bfloat162float(h1)));
        *reinterpret_cast<uint32_t*>(Olo + (row0 + 8) * DM + cc) =
            pack2(__float2bfloat16(y2 - __bfloat162float(h2)),
                  __float2bfloat16(y3 - __bfloat162float(h3)));
    }
}

// =================================================================
// launch
// =================================================================
extern "C" void kernel_launch(void* const* d_in, const int* in_sizes, int n_in,
                              void* d_out, int out_size)
{
    const float* q    = (const float*)d_in[0];
    const float* k    = (const float*)d_in[1];
    const float* v    = (const float*)d_in[2];
    const int*   mask = (const int*)d_in[3];
    const float* Wq   = (const float*)d_in[4];
    const float* bq   = (const float*)d_in[5];
    const float* Wk   = (const float*)d_in[6];
    const float* bk   = (const float*)d_in[7];
    const float* Wv   = (const float*)d_in[8];
    const float* bv   = (const float*)d_in[9];
    const float* Wo   = (const float*)d_in[10];
    const float* bo   = (const float*)d_in[11];

    __nv_bfloat16 *x0h, *x0l, *x1h, *x1l, *x2h, *x2l;
    __nv_bfloat16 *w0h, *w0l, *w1h, *w1l, *w2h, *w2l, *w3h, *w3l;
    __nv_bfloat16 *qhi, *qlo, *kchi, *kclo, *vchi, *vclo, *vthi, *vtlo, *ahi, *alo;
    int *cidx, *nact;
    cudaGetSymbolAddress((void**)&x0h, g_x0hi); cudaGetSymbolAddress((void**)&x0l, g_x0lo);
    cudaGetSymbolAddress((void**)&x1h, g_x1hi); cudaGetSymbolAddress((void**)&x1l, g_x1lo);
    cudaGetSymbolAddress((void**)&x2h, g_x2hi); cudaGetSymbolAddress((void**)&x2l, g_x2lo);
    cudaGetSymbolAddress((void**)&w0h, g_w0hi); cudaGetSymbolAddress((void**)&w0l, g_w0lo);
    cudaGetSymbolAddress((void**)&w1h, g_w1hi); cudaGetSymbolAddress((void**)&w1l, g_w1lo);
    cudaGetSymbolAddress((void**)&w2h, g_w2hi); cudaGetSymbolAddress((void**)&w2l, g_w2lo);
    cudaGetSymbolAddress((void**)&w3h, g_w3hi); cudaGetSymbolAddress((void**)&w3l, g_w3lo);
    cudaGetSymbolAddress((void**)&qhi, g_qhi);  cudaGetSymbolAddress((void**)&qlo, g_qlo);
    cudaGetSymbolAddress((void**)&kchi, g_kchi); cudaGetSymbolAddress((void**)&kclo, g_kclo);
    cudaGetSymbolAddress((void**)&vchi, g_vchi); cudaGetSymbolAddress((void**)&vclo, g_vclo);
    cudaGetSymbolAddress((void**)&vthi, g_vthi); cudaGetSymbolAddress((void**)&vtlo, g_vtlo);
    cudaGetSymbolAddress((void**)&ahi, g_ahi);  cudaGetSymbolAddress((void**)&alo, g_alo);
    cudaGetSymbolAddress((void**)&cidx, g_cidx);
    cudaGetSymbolAddress((void**)&nact, g_nact);

    cudaFuncSetAttribute(gemm_mma2, cudaFuncAttributeMaxDynamicSharedMemorySize, 2 * GSTG);
    cudaFuncSetAttribute(flash_mma, cudaFuncAttributeMaxDynamicSharedMemorySize, FTOT);

    const int NX = ML * DM;
    const int NW = DM * DM;

    compact_mask<<<BB, 256>>>(mask, cidx, nact);

    // fused splits: 3 activations + 4 weights in one launch
    SP sp{};
    sp.src[0] = q;  sp.hi[0] = x0h; sp.lo[0] = x0l; sp.n[0] = NX;
    sp.src[1] = k;  sp.hi[1] = x1h; sp.lo[1] = x1l; sp.n[1] = NX;
    sp.src[2] = v;  sp.hi[2] = x2h; sp.lo[2] = x2l; sp.n[2] = NX;
    sp.src[3] = Wq; sp.hi[3] = w0h; sp.lo[3] = w0l; sp.n[3] = NW;
    sp.src[4] = Wk; sp.hi[4] = w1h; sp.lo[4] = w1l; sp.n[4] = NW;
    sp.src[5] = Wv; sp.hi[5] = w2h; sp.lo[5] = w2l; sp.n[5] = NW;
    sp.src[6] = Wo; sp.hi[6] = w3h; sp.lo[6] = w3l; sp.n[6] = NW;
    split_all<<<dim3(1024, 7), 256>>>(sp);

    GP p{};
    p.cidx = cidx; p.nact = nact;
    // z=0: Q projection -> scaled bf16 split, full rows
    p.Ahi[0] = x0h; p.Alo[0] = x0l; p.Bhi[0] = w0h; p.Blo[0] = w0l;
    p.bias[0] = bq; p.Yhi[0] = qhi; p.Ylo[0] = qlo;
    p.scale[0] = 0.18033688011112042f;  // 0.125 * log2(e)
    p.mode[0] = 1; p.gather[0] = 0;
    // z=1: K projection -> compacted rows, compact head layout
    p.Ahi[1] = x1h; p.Alo[1] = x1l; p.Bhi[1] = w1h; p.Blo[1] = w1l;
    p.bias[1] = bk; p.Yhi[1] = kchi; p.Ylo[1] = kclo;
    p.mode[1] = 2; p.gather[1] = 1;
    // z=2: V projection -> compacted rows, compact head layout
    p.Ahi[2] = x2h; p.Alo[2] = x2l; p.Bhi[2] = w2h; p.Blo[2] = w2l;
    p.bias[2] = bv; p.Yhi[2] = vchi; p.Ylo[2] = vclo;
    p.mode[2] = 2; p.gather[2] = 1;
    gemm_mma2<<<dim3(DM / 128, ML / 128, 3), 256, 2 * GSTG>>>(p);

    vtrans<<<dim3(LL / 128, NH, BB), 256>>>(vchi, vclo, nact, vthi, vtlo);

    flash_mma<<<dim3(LL / 128, NH, BB), 256, FTOT>>>(qhi, qlo, kchi, kclo, vthi, vtlo,
                                                     nact, ahi, alo);

    GP p2{};
    p2.cidx = cidx; p2.nact = nact;
    p2.Ahi[0] = ahi; p2.Alo[0] = alo; p2.Bhi[0] = w3h; p2.Blo[0] = w3l;
    p2.bias[0] = bo; p2.Yf[0] = (float*)d_out; p2.mode[0] = 0; p2.gather[0] = 0;
    gemm_mma2<<<dim3(DM / 128, ML / 128, 1), 256, 2 * GSTG>>>(p2);
}

// round 17
// speedup vs baseline: 1.0508x; 1.0448x over previous
#include <cuda_runtime.h>
#include <cuda_bf16.h>
#include <cstdint>

#define DM 1024
#define NH 16
#define HD 64
#define BB 2
#define LL 2048
#define ML (BB * LL)  // 4096 total rows

// ---------------- scratch (no allocation allowed) ----------------
__device__ __nv_bfloat16 g_x0hi[ML * DM], g_x0lo[ML * DM];
__device__ __nv_bfloat16 g_x1hi[ML * DM], g_x1lo[ML * DM];
__device__ __nv_bfloat16 g_x2hi[ML * DM], g_x2lo[ML * DM];
__device__ __nv_bfloat16 g_w0hi[DM * DM], g_w0lo[DM * DM];
__device__ __nv_bfloat16 g_w1hi[DM * DM], g_w1lo[DM * DM];
__device__ __nv_bfloat16 g_w2hi[DM * DM], g_w2lo[DM * DM];
__device__ __nv_bfloat16 g_w3hi[DM * DM], g_w3lo[DM * DM];
__device__ __nv_bfloat16 g_qhi[ML * DM], g_qlo[ML * DM];
__device__ __nv_bfloat16 g_kchi[BB * NH * LL * HD], g_kclo[BB * NH * LL * HD];
__device__ __nv_bfloat16 g_vchi[BB * NH * LL * HD], g_vclo[BB * NH * LL * HD];
__device__ __nv_bfloat16 g_vthi[BB * NH * HD * LL], g_vtlo[BB * NH * HD * LL];
__device__ __nv_bfloat16 g_ahi[ML * DM], g_alo[ML * DM];  // flash output (split)
__device__ int g_cidx[BB * LL];
__device__ int g_nact[BB];

// ================= helpers (base compute_103 PTX only) ==========
__device__ __forceinline__ uint32_t smem_u32(const void* p) {
    uint32_t a;
    asm("{ .reg .u64 t; cvta.to.shared.u64 t, %1; cvt.u32.u64 %0, t; }" : "=r"(a) : "l"(p));
    return a;
}
__device__ __forceinline__ void ldm_x4(uint32_t* r, uint32_t addr) {
    asm volatile("ldmatrix.sync.aligned.m8n8.x4.shared.b16 {%0,%1,%2,%3}, [%4];"
                 : "=r"(r[0]), "=r"(r[1]), "=r"(r[2]), "=r"(r[3]) : "r"(addr));
}
__device__ __forceinline__ void ldm_x2(uint32_t* r, uint32_t addr) {
    asm volatile("ldmatrix.sync.aligned.m8n8.x2.shared.b16 {%0,%1}, [%2];"
                 : "=r"(r[0]), "=r"(r[1]) : "r"(addr));
}
__device__ __forceinline__ void mma16816(float* c, const uint32_t* a, const uint32_t* b) {
    asm volatile("mma.sync.aligned.m16n8k16.row.col.f32.bf16.bf16.f32 "
                 "{%0,%1,%2,%3}, {%4,%5,%6,%7}, {%8,%9}, {%0,%1,%2,%3};"
                 : "+f"(c[0]), "+f"(c[1]), "+f"(c[2]), "+f"(c[3])
                 : "r"(a[0]), "r"(a[1]), "r"(a[2]), "r"(a[3]), "r"(b[0]), "r"(b[1]));
}
__device__ __forceinline__ float ex2(float x) {
    float y;
    asm("ex2.approx.ftz.f32 %0, %1;" : "=f"(y) : "f"(x));
    return y;
}
__device__ __forceinline__ uint32_t pack2(__nv_bfloat16 a, __nv_bfloat16 b) {
    __nv_bfloat162 t = __halves2bfloat162(a, b);
    return *reinterpret_cast<uint32_t*>(&t);
}
#define CP16(d, s) asm volatile("cp.async.cg.shared.global [%0], [%1], 16;" :: "r"(d), "l"(s))
#define CPCOMMIT() asm volatile("cp.async.commit_group;" ::: "memory")
#define CPWAIT0()  asm volatile("cp.async.wait_group 0;" ::: "memory")

// =================================================================
// fused split: all 7 fp32 arrays -> bf16 hi/lo in one launch
// =================================================================
struct SP {
    const float* src[7];
    __nv_bfloat16* hi[7];
    __nv_bfloat16* lo[7];
    int n[7];
};

__global__ __launch_bounds__(256)
void split_all(SP sp)
{
    const int s = blockIdx.y;
    const float* __restrict__ x = sp.src[s];
    __nv_bfloat16* __restrict__ hi = sp.hi[s];
    __nv_bfloat16* __restrict__ lo = sp.lo[s];
    const int n = sp.n[s];
    const int stride = gridDim.x * 1024;
    for (int i = (blockIdx.x * 256 + threadIdx.x) * 4; i < n; i += stride) {
        float4 f = *reinterpret_cast<const float4*>(x + i);
        __nv_bfloat16 h0 = __float2bfloat16(f.x);
        __nv_bfloat16 h1 = __float2bfloat16(f.y);
        __nv_bfloat16 h2 = __float2bfloat16(f.z);
        __nv_bfloat16 h3 = __float2bfloat16(f.w);
        *reinterpret_cast<uint32_t*>(hi + i)     = pack2(h0, h1);
        *reinterpret_cast<uint32_t*>(hi + i + 2) = pack2(h2, h3);
        *reinterpret_cast<uint32_t*>(lo + i) =
            pack2(__float2bfloat16(f.x - __bfloat162float(h0)),
                  __float2bfloat16(f.y - __bfloat162float(h1)));
        *reinterpret_cast<uint32_t*>(lo + i + 2) =
            pack2(__float2bfloat16(f.z - __bfloat162float(h2)),
                  __float2bfloat16(f.w - __bfloat162float(h3)));
    }
}

// =================================================================
// mask compaction (deterministic, parallel scan)
// =================================================================
__global__ __launch_bounds__(256)
void compact_mask(const int* __restrict__ mask, int* __restrict__ cidx,
                  int* __restrict__ nact)
{
    int b = blockIdx.x, tid = threadIdx.x;
    __shared__ int ws[256];
    const int* mb = mask + b * LL;
    int base = tid * 8;
    int loc[8];
    int cnt = 0;
#pragma unroll
    for (int i = 0; i < 8; i++) { loc[i] = cnt; cnt += (mb[base + i] == 0); }
    ws[tid] = cnt;
    __syncthreads();
    // Hillis-Steele inclusive scan
#pragma unroll
    for (int o = 1; o < 256; o <<= 1) {
        int add = (tid >= o) ? ws[tid - o] : 0;
        __syncthreads();
        ws[tid] += add;
        __syncthreads();
    }
    if (tid == 255) nact[b] = ws[255];
    int off = ws[tid] - cnt;  // exclusive
#pragma unroll
    for (int i = 0; i < 8; i++)
        if (mb[base + i] == 0) cidx[b * LL + off + loc[i]] = base + i;
}

// =================================================================
// cp.async double-buffered GEMM, batched over z.
// NOTE: no min-blocks clause — the R12 (256,2) cap forced spills.
// =================================================================
#define LDK 40
#define GSTG 40960

struct GP {
    const __nv_bfloat16 *Ahi[3], *Alo[3], *Bhi[3], *Blo[3];
    const float* bias[3];
    float* Yf[3];
    __nv_bfloat16 *Yhi[3], *Ylo[3];
    float scale[3];
    int mode[3];
    int gather[3];
    const int* cidx;
    const int* nact;
};

__global__ __launch_bounds__(256)
void gemm_mma2(GP p)
{
    extern __shared__ char smem[];
    __shared__ int sidx[128];
    const int z = blockIdx.z;
    const __nv_bfloat16* __restrict__ Ahi = p.Ahi[z];
    const __nv_bfloat16* __restrict__ Alo = p.Alo[z];
    const __nv_bfloat16* __restrict__ Bhi = p.Bhi[z];
    const __nv_bfloat16* __restrict__ Blo = p.Blo[z];
    const float* __restrict__ bias = p.bias[z];

    const int tid = threadIdx.x, lane = tid & 31, wid = tid >> 5;
    const int wm = wid & 1, wn = wid >> 1;
    const int bm = blockIdx.y * 128, bn = blockIdx.x * 128;
    const int gflag = p.gather[z];
    const int b = bm >> 11;  // batch (LL=2048)
    const uint32_t su = smem_u32(smem);

    if (gflag) {
        int na = p.nact[b];
        int bound = (na + 63) & ~63;
        int gi0 = bm & (LL - 1);
        if (gi0 >= bound) return;
        if (tid < 128) {
            int gi = gi0 + tid;
            int gcl = gi < na ? gi : na - 1;
            sidx[tid] = p.cidx[b * LL + gcl];
        }
        __syncthreads();
    }

    float acc[4][4][4];
#pragma unroll
    for (int mt = 0; mt < 4; mt++)
#pragma unroll
        for (int nt = 0; nt < 4; nt++)
#pragma unroll
            for (int e = 0; e < 4; e++) acc[mt][nt][e] = 0.f;

    const uint32_t aoff = (uint32_t)(((lane & 15) * LDK + (lane >> 4) * 8) * 2);
    const uint32_t boff = (uint32_t)(((lane & 7) * LDK + ((lane >> 3) & 1) * 8) * 2);

    auto issue = [&](int s, int c) {
        uint32_t sb = su + (uint32_t)s * GSTG;
        int k0 = c * 32;
#pragma unroll
        for (int rep = 0; rep < 2; rep++) {
            int ch = tid + rep * 256;              // 0..511: 128 rows x 4 segs (64B/row)
            int row = ch >> 2, seg = ch & 3;
            uint32_t doff = (uint32_t)(row * 80 + seg * 16);
            size_t arow = gflag ? (size_t)(b * LL + sidx[row]) : (size_t)(bm + row);
            size_t goA = arow * DM + k0 + seg * 8;
            size_t goB = (size_t)(bn + row) * DM + k0 + seg * 8;
            CP16(sb + doff,         Ahi + goA);
            CP16(sb + 10240 + doff, Alo + goA);
            CP16(sb + 20480 + doff, Bhi + goB);
            CP16(sb + 30720 + doff, Blo + goB);
        }
    };

    issue(0, 0);
    CPCOMMIT();

    for (int c = 0; c < 32; c++) {
        CPWAIT0();
        __syncthreads();
        if (c + 1 < 32) { issue((c + 1) & 1, c + 1); CPCOMMIT(); }
        const uint32_t sb = su + (uint32_t)(c & 1) * GSTG;
        const uint32_t uAh = sb, uAl = sb + 10240, uBh = sb + 20480, uBl = sb + 30720;
#pragma unroll
        for (int ks = 0; ks < 2; ks++) {
            const uint32_t kb = (uint32_t)(ks * 32);
            uint32_t ah[4][4], al[4][4], bh[4][2], bl[4][2];
#pragma unroll
            for (int mt = 0; mt < 4; mt++) {
                uint32_t r = (uint32_t)((wm * 64 + mt * 16) * LDK * 2) + aoff + kb;
                ldm_x4(ah[mt], uAh + r);
                ldm_x4(al[mt], uAl + r);
            }
#pragma unroll
            for (int nt = 0; nt < 4; nt++) {
                uint32_t r = (uint32_t)((wn * 32 + nt * 8) * LDK * 2) + boff + kb;
                ldm_x2(bh[nt], uBh + r);
                ldm_x2(bl[nt], uBl + r);
            }
#pragma unroll
            for (int mt = 0; mt < 4; mt++)
#pragma unroll
                for (int nt = 0; nt < 4; nt++) {
                    mma16816(acc[mt][nt], ah[mt], bh[nt]);
                    mma16816(acc[mt][nt], ah[mt], bl[nt]);
                    mma16816(acc[mt][nt], al[mt], bh[nt]);
                }
        }
    }

    const int mode = p.mode[z];
    if (mode == 0) {
        float* Y = p.Yf[z];
#pragma unroll
        for (int mt = 0; mt < 4; mt++) {
            int r0 = bm + wm * 64 + mt * 16 + (lane >> 2);
#pragma unroll
            for (int nt = 0; nt < 4; nt++) {
                int c0 = bn + wn * 32 + nt * 8 + (lane & 3) * 2;
                float bx = bias[c0], by = bias[c0 + 1];
                *reinterpret_cast<float2*>(Y + (size_t)r0 * DM + c0) =
                    make_float2(acc[mt][nt][0] + bx, acc[mt][nt][1] + by);
                *reinterpret_cast<float2*>(Y + (size_t)(r0 + 8) * DM + c0) =
                    make_float2(acc[mt][nt][2] + bx, acc[mt][nt][3] + by);
            }
        }
    } else if (mode == 1) {
        __nv_bfloat16* Yh = p.Yhi[z];
        __nv_bfloat16* Yl = p.Ylo[z];
        const float sc = p.scale[z];
#pragma unroll
        for (int mt = 0; mt < 4; mt++) {
            int r0 = bm + wm * 64 + mt * 16 + (lane >> 2);
#pragma unroll
            for (int nt = 0; nt < 4; nt++) {
                int c0 = bn + wn * 32 + nt * 8 + (lane & 3) * 2;
                float bx = bias[c0], by = bias[c0 + 1];
                float y0 = (acc[mt][nt][0] + bx) * sc;
                float y1 = (acc[mt][nt][1] + by) * sc;
                float y2 = (acc[mt][nt][2] + bx) * sc;
                float y3 = (acc[mt][nt][3] + by) * sc;
                __nv_bfloat16 h0 = __float2bfloat16(y0), h1 = __float2bfloat16(y1);
                __nv_bfloat16 h2 = __float2bfloat16(y2), h3 = __float2bfloat16(y3);
                *reinterpret_cast<uint32_t*>(Yh + (size_t)r0 * DM + c0) = pack2(h0, h1);
                *reinterpret_cast<uint32_t*>(Yh + (size_t)(r0 + 8) * DM + c0) = pack2(h2, h3);
                *reinterpret_cast<uint32_t*>(Yl + (size_t)r0 * DM + c0) =
                    pack2(__float2bfloat16(y0 - __bfloat162float(h0)),
                          __float2bfloat16(y1 - __bfloat162float(h1)));
                *reinterpret_cast<uint32_t*>(Yl + (size_t)(r0 + 8) * DM + c0) =
                    pack2(__float2bfloat16(y2 - __bfloat162float(h2)),
                          __float2bfloat16(y3 - __bfloat162float(h3)));
            }
        }
    } else {  // mode 2: compact head layout [b,h][key][HD]
        __nv_bfloat16* Yh = p.Yhi[z];
        __nv_bfloat16* Yl = p.Ylo[z];
#pragma unroll
        for (int mt = 0; mt < 4; mt++) {
            int r0 = bm + wm * 64 + mt * 16 + (lane >> 2);
            int key = r0 & (LL - 1);
#pragma unroll
            for (int nt = 0; nt < 4; nt++) {
                int c0 = bn + wn * 32 + nt * 8 + (lane & 3) * 2;
                int hh = c0 >> 6, d = c0 & 63;
                size_t base = ((size_t)(b * NH + hh) * LL + key) * HD + d;
                float bx = bias[c0], by = bias[c0 + 1];
                float y0 = acc[mt][nt][0] + bx;
                float y1 = acc[mt][nt][1] + by;
                float y2 = acc[mt][nt][2] + bx;
                float y3 = acc[mt][nt][3] + by;
                __nv_bfloat16 h0 = __float2bfloat16(y0), h1 = __float2bfloat16(y1);
                __nv_bfloat16 h2 = __float2bfloat16(y2), h3 = __float2bfloat16(y3);
                *reinterpret_cast<uint32_t*>(Yh + base) = pack2(h0, h1);
                *reinterpret_cast<uint32_t*>(Yh + base + 8 * HD) = pack2(h2, h3);
                *reinterpret_cast<uint32_t*>(Yl + base) =
                    pack2(__float2bfloat16(y0 - __bfloat162float(h0)),
                          __float2bfloat16(y1 - __bfloat162float(h1)));
                *reinterpret_cast<uint32_t*>(Yl + base + 8 * HD) =
                    pack2(__float2bfloat16(y2 - __bfloat162float(h2)),
                          __float2bfloat16(y3 - __bfloat162float(h3)));
            }
        }
    }
}

// =================================================================
// V transpose: hi and lo processed concurrently (one barrier)
// =================================================================
__global__ __launch_bounds__(256)
void vtrans(const __nv_bfloat16* __restrict__ Vc, const __nv_bfloat16* __restrict__ Vcl,
            const int* __restrict__ nact,
            __nv_bfloat16* __restrict__ Vth, __nv_bfloat16* __restrict__ Vtl)
{
    __shared__ __nv_bfloat16 sh[128 * 72];
    __shared__ __nv_bfloat16 sl[128 * 72];
    const int it = blockIdx.x, h = blockIdx.y, b = blockIdx.z;
    const int bh = b * NH + h;
    const int na = nact[b];
    const int bound = (na + 63) & ~63;
    const int k0 = it * 128;
    if (k0 >= bound) return;
    const int tid = threadIdx.x;
    const int d = tid >> 2, ks = (tid & 3) * 32;

    for (int i = tid; i < 128 * 8; i += 256) {
        int row = i >> 3, seg = i & 7;
        size_t g = ((size_t)bh * LL + k0 + row) * HD + seg * 8;
        *reinterpret_cast<float4*>(&sh[row * 72 + seg * 8]) =
            *reinterpret_cast<const float4*>(Vc + g);
        *reinterpret_cast<float4*>(&sl[row * 72 + seg * 8]) =
            *reinterpret_cast<const float4*>(Vcl + g);
    }
    __syncthreads();
    __nv_bfloat16 bufh[32], bufl[32];
#pragma unroll
    for (int j = 0; j < 32; j++) {
        bufh[j] = sh[(ks + j) * 72 + d];
        bufl[j] = sl[(ks + j) * 72 + d];
    }
    size_t o = ((size_t)bh * HD + d) * LL + k0 + ks;
    float4* dph = reinterpret_cast<float4*>(Vth + o);
    float4* dpl = reinterpret_cast<float4*>(Vtl + o);
    const float4* bph = reinterpret_cast<const float4*>(bufh);
    const float4* bpl = reinterpret_cast<const float4*>(bufl);
#pragma unroll
    for (int j = 0; j < 4; j++) { dph[j] = bph[j]; dpl[j] = bpl[j]; }
}

// =================================================================
// Flash attention, mma.sync + cp.async double-buffered K/V tiles.
// Interleaved P-pack/PV; no occupancy cap.
// =================================================================
#define FQH 0
#define FQL 18432
#define FSB 36864
#define FSTG 36864
#define FTOT (FSB + 2 * FSTG)  // 110592

__global__ __launch_bounds__(256)
void flash_mma(const __nv_bfloat16* __restrict__ Qhi, const __nv_bfloat16* __restrict__ Qlo,
               const __nv_bfloat16* __restrict__ Kchi, const __nv_bfloat16* __restrict__ Kclo,
               const __nv_bfloat16* __restrict__ Vthi, const __nv_bfloat16* __restrict__ Vtlo,
               const int* __restrict__ nact,
               __nv_bfloat16* __restrict__ Ohi, __nv_bfloat16* __restrict__ Olo)
{
    extern __shared__ char smem[];
    const int qt = blockIdx.x, h = blockIdx.y, b = blockIdx.z;
    const int tid = threadIdx.x, lane = tid & 31, w = tid >> 5;
    const int bh = b * NH + h;
    const int na = nact[b];
    const int ktiles = (na + 63) >> 6;
    const uint32_t su = smem_u32(smem);

    {
        const __nv_bfloat16* qh = Qhi + ((size_t)(b * LL + qt * 128)) * DM + h * HD;
        const __nv_bfloat16* ql = Qlo + ((size_t)(b * LL + qt * 128)) * DM + h * HD;
        for (int idx = tid; idx < 1024; idx += 256) {
            int row = idx >> 3, seg = idx & 7;
            *reinterpret_cast<float4*>(smem + FQH + row * 144 + seg * 16) =
                *reinterpret_cast<const float4*>(qh + (size_t)row * DM + seg * 8);
            *reinterpret_cast<float4*>(smem + FQL + row * 144 + seg * 16) =
                *reinterpret_cast<const float4*>(ql + (size_t)row * DM + seg * 8);
        }
    }

    auto issue = [&](int s, int kt) {
        uint32_t sb = su + FSB + (uint32_t)s * FSTG;
        const __nv_bfloat16* kh = Kchi + ((size_t)bh * LL + kt * 64) * HD;
        const __nv_bfloat16* kl = Kclo + ((size_t)bh * LL + kt * 64) * HD;
        const __nv_bfloat16* vh = Vthi + (size_t)bh * HD * LL + kt * 64;
        const __nv_bfloat16* vl = Vtlo + (size_t)bh * HD * LL + kt * 64;
#pragma unroll
        for (int rep = 0; rep < 2; rep++) {
            int ch = tid + rep * 256;
            int row = ch >> 3, seg = ch & 7;
            uint32_t doff = (uint32_t)(row * 144 + seg * 16);
            CP16(sb + doff,          kh + (size_t)row * HD + seg * 8);
            CP16(sb + 9216 + doff,   kl + (size_t)row * HD + seg * 8);
            CP16(sb + 18432 + doff,  vh + (size_t)row * LL + seg * 8);
            CP16(sb + 27648 + doff,  vl + (size_t)row * LL + seg * 8);
        }
    };

    float m0 = -3.0e38f, m1 = -3.0e38f, l0 = 0.f, l1 = 0.f;
    float oacc[8][4];
#pragma unroll
    for (int nt = 0; nt < 8; nt++)
#pragma unroll
        for (int e = 0; e < 4; e++) oacc[nt][e] = 0.f;

    const uint32_t qaoff = (uint32_t)(((lane & 15) * 72 + (lane >> 4) * 8) * 2);
    const uint32_t boff  = (uint32_t)(((lane & 7) * 72 + ((lane >> 3) & 1) * 8) * 2);
    const uint32_t qrowoff = (uint32_t)(w * 16 * 144);

    issue(0, 0);
    CPCOMMIT();

    for (int kt = 0; kt < ktiles; kt++) {
        CPWAIT0();
        __syncthreads();
        if (kt + 1 < ktiles) { issue((kt + 1) & 1, kt + 1); CPCOMMIT(); }
        const uint32_t sb = su + FSB + (uint32_t)(kt & 1) * FSTG;
        const uint32_t uKH = sb, uKL = sb + 9216, uVH = sb + 18432, uVL = sb + 27648;

        float sacc[8][4];
#pragma unroll
        for (int nt = 0; nt < 8; nt++)
#pragma unroll
            for (int e = 0; e < 4; e++) sacc[nt][e] = 0.f;

#pragma unroll
        for (int ks = 0; ks < 4; ks++) {
            uint32_t ah[4], al[4];
            ldm_x4(ah, su + FQH + qrowoff + qaoff + ks * 32);
            ldm_x4(al, su + FQL + qrowoff + qaoff + ks * 32);
#pragma unroll
            for (int nt = 0; nt < 8; nt++) {
                uint32_t bh2[2], bl2[2];
                ldm_x2(bh2, uKH + nt * 1152 + boff + ks * 32);
                ldm_x2(bl2, uKL + nt * 1152 + boff + ks * 32);
                mma16816(sacc[nt], ah, bh2);
                mma16816(sacc[nt], ah, bl2);
                mma16816(sacc[nt], al, bh2);
            }
        }

        if (kt == ktiles - 1) {
            int jb = kt * 64 + 2 * (lane & 3);
#pragma unroll
            for (int nt = 0; nt < 8; nt++) {
                if (jb + nt * 8     >= na) { sacc[nt][0] = -1e30f; sacc[nt][2] = -1e30f; }
                if (jb + nt * 8 + 1 >= na) { sacc[nt][1] = -1e30f; sacc[nt][3] = -1e30f; }
            }
        }

        float rm0 = -3.0e38f, rm1 = -3.0e38f;
#pragma unroll
        for (int nt = 0; nt < 8; nt++) {
            rm0 = fmaxf(rm0, fmaxf(sacc[nt][0], sacc[nt][1]));
            rm1 = fmaxf(rm1, fmaxf(sacc[nt][2], sacc[nt][3]));
        }
        rm0 = fmaxf(rm0, __shfl_xor_sync(0xffffffffu, rm0, 1));
        rm0 = fmaxf(rm0, __shfl_xor_sync(0xffffffffu, rm0, 2));
        rm1 = fmaxf(rm1, __shfl_xor_sync(0xffffffffu, rm1, 1));
        rm1 = fmaxf(rm1, __shfl_xor_sync(0xffffffffu, rm1, 2));
        float mn0 = fmaxf(m0, rm0), mn1 = fmaxf(m1, rm1);
        float c0 = ex2(m0 - mn0), c1 = ex2(m1 - mn1);
        m0 = mn0; m1 = mn1;

#pragma unroll
        for (int nt = 0; nt < 8; nt++) {
            oacc[nt][0] *= c0; oacc[nt][1] *= c0;
            oacc[nt][2] *= c1; oacc[nt][3] *= c1;
        }

        float rs0 = 0.f, rs1 = 0.f;
#pragma unroll
        for (int t = 0; t < 4; t++) {
            uint32_t pah4[4], pal4[4];
#pragma unroll
            for (int e = 0; e < 2; e++) {
                int nt = 2 * t + e;
                float p0 = ex2(sacc[nt][0] - mn0);
                float p1 = ex2(sacc[nt][1] - mn0);
                float p2 = ex2(sacc[nt][2] - mn1);
                float p3 = ex2(sacc[nt][3] - mn1);
                rs0 += p0 + p1;
                rs1 += p2 + p3;
                __nv_bfloat16 h0 = __float2bfloat16(p0), h1 = __float2bfloat16(p1);
                __nv_bfloat16 h2 = __float2bfloat16(p2), h3 = __float2bfloat16(p3);
                pah4[2 * e]     = pack2(h0, h1);
                pah4[2 * e + 1] = pack2(h2, h3);
                pal4[2 * e]     = pack2(__float2bfloat16(p0 - __bfloat162float(h0)),
                                        __float2bfloat16(p1 - __bfloat162float(h1)));
                pal4[2 * e + 1] = pack2(__float2bfloat16(p2 - __bfloat162float(h2)),
                                        __float2bfloat16(p3 - __bfloat162float(h3)));
            }
#pragma unroll
            for (int nt = 0; nt < 8; nt++) {
                uint32_t bvh[2], bvl[2];
                ldm_x2(bvh, uVH + nt * 1152 + boff + t * 32);
                ldm_x2(bvl, uVL + nt * 1152 + boff + t * 32);
                mma16816(oacc[nt], pah4, bvh);
                mma16816(oacc[nt], pah4, bvl);
                mma16816(oacc[nt], pal4, bvh);
            }
        }
        rs0 += __shfl_xor_sync(0xffffffffu, rs0, 1);
        rs0 += __shfl_xor_sync(0xffffffffu, rs0, 2);
        rs1 += __shfl_xor_sync(0xffffffffu, rs1, 1);
        rs1 += __shfl_xor_sync(0xffffffffu, rs1, 2);
        l0 = l0 * c0 + rs0;
        l1 = l1 * c1 + rs1;
    }

    float i0 = 1.f / l0, i1 = 1.f / l1;
    int r = lane >> 2;
    size_t row0 = (size_t)b * LL + qt * 128 + w * 16 + r;
    int cc0 = h * HD + 2 * (lane & 3);
#pragma unroll
    for (int nt = 0; nt < 8; nt++) {
        int cc = cc0 + nt * 8;
        float y0 = oacc[nt][0] * i0, y1 = oacc[nt][1] * i0;
        float y2 = oacc[nt][2] * i1, y3 = oacc[nt][3] * i1;
        __nv_bfloat16 h0 = __float2bfloat16(y0), h1 = __float2bfloat16(y1);
        __nv_bfloat16 h2 = __float2bfloat16(y2), h3 = __float2bfloat16(y3);
        *reinterpret_cast<uint32_t*>(Ohi + row0 * DM + cc) = pack2(h0, h1);
        *reinterpret_cast<uint32_t*>(Ohi + (row0 + 8) * DM + cc) = pack2(h2, h3);
        *reinterpret_cast<uint32_t*>(Olo + row0 * DM + cc) =
            pack2(__float2bfloat16(y0 - __bfloat162float(h0)),
                  __float2bfloat16(y1 - __bfloat162float(h1)));
        *reinterpret_cast<uint32_t*>(Olo + (row0 + 8) * DM + cc) =
            pack2(__float2bfloat16(y2 - __bfloat162float(h2)),
                  __float2bfloat16(y3 - __bfloat162float(h3)));
    }
}

// =================================================================
// launch
// =================================================================
extern "C" void kernel_launch(void* const* d_in, const int* in_sizes, int n_in,
                              void* d_out, int out_size)
{
    const float* q    = (const float*)d_in[0];
    const float* k    = (const float*)d_in[1];
    const float* v    = (const float*)d_in[2];
    const int*   mask = (const int*)d_in[3];
    const float* Wq   = (const float*)d_in[4];
    const float* bq   = (const float*)d_in[5];
    const float* Wk   = (const float*)d_in[6];
    const float* bk   = (const float*)d_in[7];
    const float* Wv   = (const float*)d_in[8];
    const float* bv   = (const float*)d_in[9];
    const float* Wo   = (const float*)d_in[10];
    const float* bo   = (const float*)d_in[11];

    __nv_bfloat16 *x0h, *x0l, *x1h, *x1l, *x2h, *x2l;
    __nv_bfloat16 *w0h, *w0l, *w1h, *w1l, *w2h, *w2l, *w3h, *w3l;
    __nv_bfloat16 *qhi, *qlo, *kchi, *kclo, *vchi, *vclo, *vthi, *vtlo, *ahi, *alo;
    int *cidx, *nact;
    cudaGetSymbolAddress((void**)&x0h, g_x0hi); cudaGetSymbolAddress((void**)&x0l, g_x0lo);
    cudaGetSymbolAddress((void**)&x1h, g_x1hi); cudaGetSymbolAddress((void**)&x1l, g_x1lo);
    cudaGetSymbolAddress((void**)&x2h, g_x2hi); cudaGetSymbolAddress((void**)&x2l, g_x2lo);
    cudaGetSymbolAddress((void**)&w0h, g_w0hi); cudaGetSymbolAddress((void**)&w0l, g_w0lo);
    cudaGetSymbolAddress((void**)&w1h, g_w1hi); cudaGetSymbolAddress((void**)&w1l, g_w1lo);
    cudaGetSymbolAddress((void**)&w2h, g_w2hi); cudaGetSymbolAddress((void**)&w2l, g_w2lo);
    cudaGetSymbolAddress((void**)&w3h, g_w3hi); cudaGetSymbolAddress((void**)&w3l, g_w3lo);
    cudaGetSymbolAddress((void**)&qhi, g_qhi);  cudaGetSymbolAddress((void**)&qlo, g_qlo);
    cudaGetSymbolAddress((void**)&kchi, g_kchi); cudaGetSymbolAddress((void**)&kclo, g_kclo);
    cudaGetSymbolAddress((void**)&vchi, g_vchi); cudaGetSymbolAddress((void**)&vclo, g_vclo);
    cudaGetSymbolAddress((void**)&vthi, g_vthi); cudaGetSymbolAddress((void**)&vtlo, g_vtlo);
    cudaGetSymbolAddress((void**)&ahi, g_ahi);  cudaGetSymbolAddress((void**)&alo, g_alo);
    cudaGetSymbolAddress((void**)&cidx, g_cidx);
    cudaGetSymbolAddress((void**)&nact, g_nact);

    cudaFuncSetAttribute(gemm_mma2, cudaFuncAttributeMaxDynamicSharedMemorySize, 2 * GSTG);
    cudaFuncSetAttribute(flash_mma, cudaFuncAttributeMaxDynamicSharedMemorySize, FTOT);

    const int NX = ML * DM;
    const int NW = DM * DM;

    compact_mask<<<BB, 256>>>(mask, cidx, nact);

    // fused splits: 3 activations + 4 weights in one launch
    SP sp{};
    sp.src[0] = q;  sp.hi[0] = x0h; sp.lo[0] = x0l; sp.n[0] = NX;
    sp.src[1] = k;  sp.hi[1] = x1h; sp.lo[1] = x1l; sp.n[1] = NX;
    sp.src[2] = v;  sp.hi[2] = x2h; sp.lo[2] = x2l; sp.n[2] = NX;
    sp.src[3] = Wq; sp.hi[3] = w0h; sp.lo[3] = w0l; sp.n[3] = NW;
    sp.src[4] = Wk; sp.hi[4] = w1h; sp.lo[4] = w1l; sp.n[4] = NW;
    sp.src[5] = Wv; sp.hi[5] = w2h; sp.lo[5] = w2l; sp.n[5] = NW;
    sp.src[6] = Wo; sp.hi[6] = w3h; sp.lo[6] = w3l; sp.n[6] = NW;
    split_all<<<dim3(1024, 7), 256>>>(sp);

    GP p{};
    p.cidx = cidx; p.nact = nact;
    // z=0: Q projection -> scaled bf16 split, full rows
    p.Ahi[0] = x0h; p.Alo[0] = x0l; p.Bhi[0] = w0h; p.Blo[0] = w0l;
    p.bias[0] = bq; p.Yhi[0] = qhi; p.Ylo[0] = qlo;
    p.scale[0] = 0.18033688011112042f;  // 0.125 * log2(e)
    p.mode[0] = 1; p.gather[0] = 0;
    // z=1: K projection -> compacted rows, compact head layout
    p.Ahi[1] = x1h; p.Alo[1] = x1l; p.Bhi[1] = w1h; p.Blo[1] = w1l;
    p.bias[1] = bk; p.Yhi[1] = kchi; p.Ylo[1] = kclo;
    p.mode[1] = 2; p.gather[1] = 1;
    // z=2: V projection -> compacted rows, compact head layout
    p.Ahi[2] = x2h; p.Alo[2] = x2l; p.Bhi[2] = w2h; p.Blo[2] = w2l;
    p.bias[2] = bv; p.Yhi[2] = vchi; p.Ylo[2] = vclo;
    p.mode[2] = 2; p.gather[2] = 1;
    gemm_mma2<<<dim3(DM / 128, ML / 128, 3), 256, 2 * GSTG>>>(p);

    vtrans<<<dim3(LL / 128, NH, BB), 256>>>(vchi, vclo, nact, vthi, vtlo);

    flash_mma<<<dim3(LL / 128, NH, BB), 256, FTOT>>>(qhi, qlo, kchi, kclo, vthi, vtlo,
                                                     nact, ahi, alo);

    GP p2{};
    p2.cidx = cidx; p2.nact = nact;
    p2.Ahi[0] = ahi; p2.Alo[0] = alo; p2.Bhi[0] = w3h; p2.Blo[0] = w3l;
    p2.bias[0] = bo; p2.Yf[0] = (float*)d_out; p2.mode[0] = 0; p2.gather[0] = 0;
    gemm_mma2<<<dim3(DM / 128, ML / 128, 1), 256, 2 * GSTG>>>(p2);
}